// round 4
// baseline (speedup 1.0000x reference)
#include <cuda_runtime.h>

#define H 256
#define NMAX 20000
#define EMAX 320000
#define GMAX 1000
#define DIS 384

typedef unsigned long long ull;

// ---------------- device scratch (static globals: no allocation APIs) ----------------
__device__ int   g_is64;
__device__ int   g_src[EMAX];
__device__ int   g_dst[EMAX];
__device__ int   g_e2g[EMAX];
__device__ float g_h[NMAX * H];
__device__ float g_P[NMAX * H];
__device__ float g_Q[NMAX * H];
__device__ float g_S[NMAX * H];
__device__ float g_R[GMAX * H];
__device__ float g_femb[(size_t)EMAX * DIS];
__device__ float g_e1[(size_t)EMAX * H];
__device__ float g_sums[NMAX * H];
__device__ float g_cnt[NMAX];
__device__ float g_rcnt[NMAX];
__device__ float g_t1[NMAX * H];

__device__ __forceinline__ float dsilu(float x) {
    return __fdividef(x, 1.0f + __expf(-x));
}

// packed f32x2 FMA: d += a * b  (two fp32 FMAs per instruction; ptxas never
// auto-generates this — PTX-only per SASS_QUICKREF)
__device__ __forceinline__ void ffma2(ull& d, ull a, ull b) {
    asm("fma.rn.f32x2 %0, %1, %2, %0;" : "+l"(d) : "l"(a), "l"(b));
}
__device__ __forceinline__ float2 upk(ull x) {
    float2 r;
    asm("mov.b64 {%0, %1}, %2;" : "=f"(r.x), "=f"(r.y) : "l"(x));
    return r;
}

// ---------------- index dtype detection + conversion (+ fused degree count) ----------
__global__ void detect_k(const void* eidx, int E) {
    __shared__ int any;
    if (threadIdx.x == 0) any = 0;
    __syncthreads();
    const int* w = (const int*)eidx;
    int lim = 2048 < (E - 1) ? 2048 : (E - 1);
    for (int i = threadIdx.x; i < lim; i += blockDim.x) {
        if (w[2 * i + 1] != 0) any = 1;
    }
    __syncthreads();
    if (threadIdx.x == 0) g_is64 = (any == 0) ? 1 : 0;
}

__global__ void convert_k(const void* eidx, const void* e2g, int E) {
    int i = blockIdx.x * blockDim.x + threadIdx.x;
    if (i >= E) return;
    int s;
    if (g_is64) {
        const long long* p = (const long long*)eidx;
        const long long* q = (const long long*)e2g;
        s = (int)p[i];
        g_dst[i] = (int)p[(size_t)E + i];
        g_e2g[i] = (int)q[i];
    } else {
        const int* p = (const int*)eidx;
        const int* q = (const int*)e2g;
        s = p[i];
        g_dst[i] = p[E + i];
        g_e2g[i] = q[i];
    }
    g_src[i] = s;
    atomicAdd(&g_cnt[s], 1.0f);
}

// ---------------- zero accumulators (every graph replay) ----------------
__global__ void zero_k(int Nn) {
    int i = blockIdx.x * blockDim.x + threadIdx.x;
    if (i < Nn * H) g_sums[i] = 0.0f;
    if (i < Nn) g_cnt[i] = 0.0f;
}

// ---------------- layernorm: one block per row ----------------
__global__ __launch_bounds__(256) void ln_k(const float* __restrict__ x,
                                            const float* __restrict__ gm,
                                            const float* __restrict__ bt) {
    int row = blockIdx.x;
    int c = threadIdx.x;
    float v = x[(size_t)row * H + c];
    float s = v, ss = v * v;
#pragma unroll
    for (int o = 16; o; o >>= 1) {
        s  += __shfl_xor_sync(0xffffffffu, s, o);
        ss += __shfl_xor_sync(0xffffffffu, ss, o);
    }
    __shared__ float as[8], bs[8];
    if ((c & 31) == 0) { as[c >> 5] = s; bs[c >> 5] = ss; }
    __syncthreads();
    s = 0.f; ss = 0.f;
#pragma unroll
    for (int i = 0; i < 8; i++) { s += as[i]; ss += bs[i]; }
    float mu  = s * (1.0f / H);
    float var = ss * (1.0f / H) - mu * mu;
    float inv = rsqrtf(var + 1e-5f);
    g_h[(size_t)row * H + c] = (v - mu) * inv * gm[c] + bt[c];
}

// ---------------- R[g] = (L@L^T).flatten() @ We1[512:521] + be1 ----------------
__global__ __launch_bounds__(256) void lat_k(const float* __restrict__ L,
                                             const float* __restrict__ We1,
                                             const float* __restrict__ be1) {
    int g = blockIdx.x;
    __shared__ float ll[9];
    if (threadIdx.x < 9) {
        int i = threadIdx.x / 3, k = threadIdx.x % 3;
        const float* Lg = L + g * 9;
        ll[threadIdx.x] = Lg[i * 3 + 0] * Lg[k * 3 + 0] +
                          Lg[i * 3 + 1] * Lg[k * 3 + 1] +
                          Lg[i * 3 + 2] * Lg[k * 3 + 2];
    }
    __syncthreads();
    int c = threadIdx.x;
    float a = be1[c];
#pragma unroll
    for (int p = 0; p < 9; p++) a += ll[p] * We1[(512 + p) * H + c];
    g_R[g * H + c] = a;
}

// ---------------- sinusoid embedding via angle-addition recurrence ----------------
__global__ __launch_bounds__(256) void femb_k(const float* __restrict__ fd, int E) {
    __shared__ float fs[32 * DIS];  // 49152 B
    const int tid = threadIdx.x;
    const int be = blockIdx.x * 32;
    if (tid < 96) {
        const int e = tid & 31;
        const int d = tid >> 5;
        const int ge = be + e;
        float x = (ge < E) ? fd[ge * 3 + d] : 0.0f;
        float th = 6.28318530717958647692f * x;
        float s1, c1;
        sincosf(th, &s1, &c1);
        int f = e;  // stagger start: bank-conflict-free fills
        float sf, cf;
        sincosf(th * (float)f, &sf, &cf);
        float* rowS = fs + e * DIS + d * 64;
        float* rowC = rowS + 192;
        for (int i = 0; i < 64; ++i) {
            rowS[f] = sf;
            rowC[f] = cf;
            f++;
            float ns = sf * c1 + cf * s1;
            float nc = cf * c1 - sf * s1;
            bool wrap = (f == 64);
            sf = wrap ? 0.0f : ns;
            cf = wrap ? 1.0f : nc;
            f  = wrap ? 0 : f;
        }
    }
    __syncthreads();
    float4* dst4 = (float4*)(g_femb + (size_t)be * DIS);
    const float4* s4 = (const float4*)fs;
    if (be + 32 <= E) {
        for (int i = tid; i < 32 * 96; i += 256) dst4[i] = s4[i];
    } else {
        for (int i = tid; i < 32 * 96; i += 256)
            if (be + i / 96 < E) dst4[i] = s4[i];
    }
}

__global__ void rcnt_k(int Nn) {
    int i = blockIdx.x * blockDim.x + threadIdx.x;
    if (i < Nn) g_rcnt[i] = 1.0f / fmaxf(g_cnt[i], 1.0f);
}

// ---------------- 64x64x16 fp32 GEMM, f32x2 packed-FMA inner loop ----------------
// A tile stored DUPLICATED in smem ([a,a] pairs) so one 64-bit LDS yields a
// broadcast operand for fma.rn.f32x2 with zero packing MOVs. Row stride 132
// floats staggers banks for the duplicated stores.
// MODE 0: C = A@W
// MODE 1: C = silu(A@W + P[src] + Q[dst] + R[e2g])
// MODE 2: atomicAdd(sums[src], silu(A@W + bias))
// MODE 3: C = silu((rowScale*A)@W + addRow + bias)
// MODE 4: C = addRow + silu(A@W + bias)
#define ASTRIDE 132
template <int MODE>
__global__ __launch_bounds__(256) void gemm_k(
    const float* __restrict__ A, const float* __restrict__ W,
    float* __restrict__ C, int M, int K,
    const int* __restrict__ src, const int* __restrict__ dst,
    const int* __restrict__ e2g,
    const float* __restrict__ Pm, const float* __restrict__ Qm,
    const float* __restrict__ Rm,
    const float* __restrict__ bias,
    const float* __restrict__ rowScale,
    const float* __restrict__ addRow) {
    __shared__ __align__(16) float As2[16 * ASTRIDE];  // duplicated pairs: 8448 B
    __shared__ __align__(16) float Bs[16 * 64];        // 4096 B

    const int tid = threadIdx.x;
    const int tx = tid & 15;
    const int ty = tid >> 4;
    const int gm = blockIdx.y * 64;
    const int gn = blockIdx.x * 64;

    const int ar = tid >> 2;         // 0..63 (A row within tile)
    const int ac = (tid & 3) << 2;   // 0,4,8,12 (A col group)
    const int arow = gm + ar;
    const int br = tid >> 4;         // 0..15
    const int bc = (tid & 15) << 2;  // 0..60

    float rs = 1.0f;
    if (MODE == 3) rs = (arow < M) ? rowScale[arow] : 0.0f;

    ull acc[4][2];
#pragma unroll
    for (int i = 0; i < 4; i++) { acc[i][0] = 0ull; acc[i][1] = 0ull; }

    const float* Ap = A + (size_t)arow * K + ac;
    const float* Wp = W + (size_t)br * H + gn + bc;
    const ull* A64 = (const ull*)As2;
    const ull* B64 = (const ull*)Bs;

    for (int k0 = 0; k0 < K; k0 += 16) {
        float4 av = make_float4(0.f, 0.f, 0.f, 0.f);
        if (arow < M) av = *(const float4*)(Ap + k0);
        if (MODE == 3) { av.x *= rs; av.y *= rs; av.z *= rs; av.w *= rs; }
        float4 bv = *(const float4*)(Wp + (size_t)k0 * H);
        __syncthreads();
        *(float2*)&As2[(ac + 0) * ASTRIDE + 2 * ar] = make_float2(av.x, av.x);
        *(float2*)&As2[(ac + 1) * ASTRIDE + 2 * ar] = make_float2(av.y, av.y);
        *(float2*)&As2[(ac + 2) * ASTRIDE + 2 * ar] = make_float2(av.z, av.z);
        *(float2*)&As2[(ac + 3) * ASTRIDE + 2 * ar] = make_float2(av.w, av.w);
        *(float4*)&Bs[br * 64 + bc] = bv;
        __syncthreads();
#pragma unroll
        for (int kk = 0; kk < 16; ++kk) {
            const ull* ap = A64 + kk * (ASTRIDE / 2) + 4 * ty;
            const ull* bp = B64 + kk * 32 + 2 * tx;
            ull b0 = bp[0], b1 = bp[1];
            ull a0 = ap[0], a1 = ap[1], a2 = ap[2], a3 = ap[3];
            ffma2(acc[0][0], a0, b0); ffma2(acc[0][1], a0, b1);
            ffma2(acc[1][0], a1, b0); ffma2(acc[1][1], a1, b1);
            ffma2(acc[2][0], a2, b0); ffma2(acc[2][1], a2, b1);
            ffma2(acc[3][0], a3, b0); ffma2(acc[3][1], a3, b1);
        }
    }

    const int col = gn + (tx << 2);
#pragma unroll
    for (int i = 0; i < 4; i++) {
        const int row = gm + (ty << 2) + i;
        if (row >= M) continue;
        float2 lo = upk(acc[i][0]);
        float2 hi = upk(acc[i][1]);
        float v0 = lo.x, v1 = lo.y, v2 = hi.x, v3 = hi.y;
        if (MODE == 0) {
            *(float4*)&C[(size_t)row * H + col] = make_float4(v0, v1, v2, v3);
        } else if (MODE == 1) {
            int s = src[row], d = dst[row], g = e2g[row];
            float4 p = *(const float4*)&Pm[(size_t)s * H + col];
            float4 q = *(const float4*)&Qm[(size_t)d * H + col];
            float4 r = *(const float4*)&Rm[(size_t)g * H + col];
            float4 o;
            o.x = dsilu(v0 + p.x + q.x + r.x);
            o.y = dsilu(v1 + p.y + q.y + r.y);
            o.z = dsilu(v2 + p.z + q.z + r.z);
            o.w = dsilu(v3 + p.w + q.w + r.w);
            *(float4*)&C[(size_t)row * H + col] = o;
        } else if (MODE == 2) {
            int s = src[row];
            float4 bb = *(const float4*)&bias[col];
            atomicAdd(&C[(size_t)s * H + col + 0], dsilu(v0 + bb.x));
            atomicAdd(&C[(size_t)s * H + col + 1], dsilu(v1 + bb.y));
            atomicAdd(&C[(size_t)s * H + col + 2], dsilu(v2 + bb.z));
            atomicAdd(&C[(size_t)s * H + col + 3], dsilu(v3 + bb.w));
        } else if (MODE == 3) {
            float4 bb = *(const float4*)&bias[col];
            float4 ad = *(const float4*)&addRow[(size_t)row * H + col];
            float4 o;
            o.x = dsilu(v0 + ad.x + bb.x);
            o.y = dsilu(v1 + ad.y + bb.y);
            o.z = dsilu(v2 + ad.z + bb.z);
            o.w = dsilu(v3 + ad.w + bb.w);
            *(float4*)&C[(size_t)row * H + col] = o;
        } else {  // MODE 4
            float4 bb = *(const float4*)&bias[col];
            float4 ad = *(const float4*)&addRow[(size_t)row * H + col];
            float4 o;
            o.x = ad.x + dsilu(v0 + bb.x);
            o.y = ad.y + dsilu(v1 + bb.y);
            o.z = ad.z + dsilu(v2 + bb.z);
            o.w = ad.w + dsilu(v3 + bb.w);
            *(float4*)&C[(size_t)row * H + col] = o;
        }
    }
}

// ---------------- host side ----------------
static float *p_h = nullptr, *p_P = nullptr, *p_Q = nullptr, *p_S = nullptr,
             *p_R = nullptr, *p_femb = nullptr, *p_e1 = nullptr,
             *p_sums = nullptr, *p_t1 = nullptr, *p_rcnt = nullptr;
static int *p_src = nullptr, *p_dst = nullptr, *p_e2g = nullptr;

static void init_ptrs() {
    if (p_h) return;
    cudaGetSymbolAddress((void**)&p_h, g_h);
    cudaGetSymbolAddress((void**)&p_P, g_P);
    cudaGetSymbolAddress((void**)&p_Q, g_Q);
    cudaGetSymbolAddress((void**)&p_S, g_S);
    cudaGetSymbolAddress((void**)&p_R, g_R);
    cudaGetSymbolAddress((void**)&p_femb, g_femb);
    cudaGetSymbolAddress((void**)&p_e1, g_e1);
    cudaGetSymbolAddress((void**)&p_sums, g_sums);
    cudaGetSymbolAddress((void**)&p_t1, g_t1);
    cudaGetSymbolAddress((void**)&p_rcnt, g_rcnt);
    cudaGetSymbolAddress((void**)&p_src, g_src);
    cudaGetSymbolAddress((void**)&p_dst, g_dst);
    cudaGetSymbolAddress((void**)&p_e2g, g_e2g);
}
namespace {
struct Boot {  // force module load before harness memory checkpoints
    Boot() { init_ptrs(); }
};
static Boot boot_;
}  // namespace

extern "C" void kernel_launch(void* const* d_in, const int* in_sizes, int n_in,
                              void* d_out, int out_size) {
    init_ptrs();
    const float* nf  = (const float*)d_in[0];
    const float* lat = (const float*)d_in[1];
    const void*  eix = d_in[2];
    const void*  e2g = d_in[3];
    const float* fd  = (const float*)d_in[4];
    // d_in[5] = num_atoms (unused by reference)
    const float* gam = (const float*)d_in[6];
    const float* bet = (const float*)d_in[7];
    const float* We1 = (const float*)d_in[8];
    const float* be1 = (const float*)d_in[9];
    const float* We2 = (const float*)d_in[10];
    const float* be2 = (const float*)d_in[11];
    const float* Wn1 = (const float*)d_in[12];
    const float* bn1 = (const float*)d_in[13];
    const float* Wn2 = (const float*)d_in[14];
    const float* bn2 = (const float*)d_in[15];
    float* out = (float*)d_out;

    const int Nn = in_sizes[0] / H;
    const int Gn = in_sizes[1] / 9;
    const int E  = in_sizes[4] / 3;

    detect_k<<<1, 256>>>(eix, E);
    zero_k<<<(Nn * H + 255) / 256, 256>>>(Nn);          // zero sums + cnt first
    convert_k<<<(E + 255) / 256, 256>>>(eix, e2g, E);   // indices + degree count
    ln_k<<<Nn, 256>>>(nf, gam, bet);
    lat_k<<<Gn, 256>>>(lat, We1, be1);
    rcnt_k<<<(Nn + 255) / 256, 256>>>(Nn);

    dim3 gN(4, (Nn + 63) / 64);
    dim3 gE(4, (E + 63) / 64);

    // node-side precomputes: P = h@We1[:H], Q = h@We1[H:2H], S = h@Wn1[:H]
    gemm_k<0><<<gN, 256>>>(p_h, We1, p_P, Nn, H, 0, 0, 0, 0, 0, 0, 0, 0, 0);
    gemm_k<0><<<gN, 256>>>(p_h, We1 + 256 * H, p_Q, Nn, H, 0, 0, 0, 0, 0, 0, 0, 0, 0);
    gemm_k<0><<<gN, 256>>>(p_h, Wn1, p_S, Nn, H, 0, 0, 0, 0, 0, 0, 0, 0, 0);

    femb_k<<<(E + 31) / 32, 256>>>(fd, E);

    // edge layer 1: e1 = silu(femb@Wf + P[src] + Q[dst] + R[e2g])
    gemm_k<1><<<gE, 256>>>(p_femb, We1 + 521 * H, p_e1, E, DIS,
                           p_src, p_dst, p_e2g, p_P, p_Q, p_R, 0, 0, 0);

    // edge layer 2 + scatter-add into sums
    gemm_k<2><<<gE, 256>>>(p_e1, We2, p_sums, E, H,
                           p_src, 0, 0, 0, 0, 0, be2, 0, 0);

    // node layer 1: t1 = silu(agg@Wn1[H:] + S + bn1), agg = sums * rcnt
    gemm_k<3><<<gN, 256>>>(p_sums, Wn1 + 256 * H, p_t1, Nn, H,
                           0, 0, 0, 0, 0, 0, bn1, p_rcnt, p_S);

    // node layer 2 + residual
    gemm_k<4><<<gN, 256>>>(p_t1, Wn2, out, Nn, H,
                           0, 0, 0, 0, 0, 0, bn2, 0, nf);
}

// round 6
// speedup vs baseline: 2.2613x; 2.2613x over previous
#include <cuda_runtime.h>
#include <cuda_bf16.h>
#include <cstdint>

#define H 256
#define NMAX 20000
#define EMAX 320000
#define GMAX 1000
#define DIS 384

typedef unsigned int u32;
typedef unsigned short us;

// ============================ helpers ============================
__device__ __forceinline__ u32 smem_u32(const void* p) {
    u32 a;
    asm("{ .reg .u64 t; cvta.to.shared.u64 t, %1; cvt.u32.u64 %0, t; }" : "=r"(a) : "l"(p));
    return a;
}
__device__ __forceinline__ u32 lds32(u32 a) {
    u32 v;
    asm volatile("ld.shared.b32 %0, [%1];" : "=r"(v) : "r"(a));
    return v;
}
__device__ __forceinline__ void cpa(u32 dst, const void* src, int sz) {
    asm volatile("cp.async.cg.shared.global [%0], [%1], 16, %2;"
                 :: "r"(dst), "l"(src), "r"(sz) : "memory");
}
__device__ __forceinline__ void cpcommit() {
    asm volatile("cp.async.commit_group;" ::: "memory");
}
template <int N>
__device__ __forceinline__ void cpwait() {
    asm volatile("cp.async.wait_group %0;" :: "n"(N) : "memory");
}
// m16n8k16 bf16 mma, fp32 accum (arch-neutral HMMA path)
__device__ __forceinline__ void mma16816(float* c, const u32* a, const u32* b) {
    asm volatile(
        "mma.sync.aligned.m16n8k16.row.col.f32.bf16.bf16.f32 "
        "{%0,%1,%2,%3},{%4,%5,%6,%7},{%8,%9},{%0,%1,%2,%3};"
        : "+f"(c[0]), "+f"(c[1]), "+f"(c[2]), "+f"(c[3])
        : "r"(a[0]), "r"(a[1]), "r"(a[2]), "r"(a[3]), "r"(b[0]), "r"(b[1]));
}
__device__ __forceinline__ float dsilu(float x) {
    return __fdividef(x, 1.0f + __expf(-x));
}
__device__ __forceinline__ void split1(float v, us& h, us& l) {
    __nv_bfloat16 bh = __float2bfloat16(v);
    float hv = __bfloat162float(bh);
    __nv_bfloat16 bl = __float2bfloat16(v - hv);
    h = *reinterpret_cast<us*>(&bh);
    l = *reinterpret_cast<us*>(&bl);
}

// ============================ device scratch ============================
__device__ int g_is64;
__device__ int g_src[EMAX];
__device__ int g_dst[EMAX];
__device__ int g_e2g[EMAX];
__device__ float g_P[NMAX * H];
__device__ float g_Q[NMAX * H];
__device__ float g_S[NMAX * H];
__device__ float g_R[GMAX * H];
__device__ float g_sums[NMAX * H];
__device__ float g_cnt[NMAX];
__device__ float g_rcnt[NMAX];
__device__ us g_hsh[NMAX * H];
__device__ us g_hsl[NMAX * H];
__device__ us g_fembh[(size_t)EMAX * DIS];
__device__ us g_fembl[(size_t)EMAX * DIS];
__device__ us g_e1h[(size_t)EMAX * H];
__device__ us g_e1l[(size_t)EMAX * H];
__device__ us g_sumh[NMAX * H];
__device__ us g_suml[NMAX * H];
__device__ us g_t1h[NMAX * H];
__device__ us g_t1l[NMAX * H];
__device__ us g_wPh[H * H],   g_wPl[H * H];
__device__ us g_wQh[H * H],   g_wQl[H * H];
__device__ us g_wSh[H * H],   g_wSl[H * H];
__device__ us g_wFh[H * DIS], g_wFl[H * DIS];
__device__ us g_w2h[H * H],   g_w2l[H * H];
__device__ us g_wNh[H * H],   g_wNl[H * H];
__device__ us g_wOh[H * H],   g_wOl[H * H];

// ============================ small kernels ============================
__global__ void detect_k(const void* eidx, int E) {
    __shared__ int any;
    if (threadIdx.x == 0) any = 0;
    __syncthreads();
    const int* w = (const int*)eidx;
    int lim = 2048 < (E - 1) ? 2048 : (E - 1);
    for (int i = threadIdx.x; i < lim; i += blockDim.x)
        if (w[2 * i + 1] != 0) any = 1;
    __syncthreads();
    if (threadIdx.x == 0) g_is64 = (any == 0) ? 1 : 0;
}

__global__ void convert_k(const void* eidx, const void* e2g, int E) {
    int i = blockIdx.x * blockDim.x + threadIdx.x;
    if (i >= E) return;
    int s;
    if (g_is64) {
        const long long* p = (const long long*)eidx;
        const long long* q = (const long long*)e2g;
        s = (int)p[i];
        g_dst[i] = (int)p[(size_t)E + i];
        g_e2g[i] = (int)q[i];
    } else {
        const int* p = (const int*)eidx;
        const int* q = (const int*)e2g;
        s = p[i];
        g_dst[i] = p[E + i];
        g_e2g[i] = q[i];
    }
    g_src[i] = s;
    atomicAdd(&g_cnt[s], 1.0f);
}

__global__ void zero_k(int Nn) {
    int i = blockIdx.x * blockDim.x + threadIdx.x;
    if (i < Nn * H) g_sums[i] = 0.0f;
    if (i < Nn) g_cnt[i] = 0.0f;
}

__global__ void rcnt_k(int Nn) {
    int i = blockIdx.x * blockDim.x + threadIdx.x;
    if (i < Nn) g_rcnt[i] = 1.0f / fmaxf(g_cnt[i], 1.0f);
}

__global__ __launch_bounds__(256) void ln_k(const float* __restrict__ x,
                                            const float* __restrict__ gm,
                                            const float* __restrict__ bt) {
    int row = blockIdx.x;
    int c = threadIdx.x;
    float v = x[(size_t)row * H + c];
    float s = v, ss = v * v;
#pragma unroll
    for (int o = 16; o; o >>= 1) {
        s  += __shfl_xor_sync(0xffffffffu, s, o);
        ss += __shfl_xor_sync(0xffffffffu, ss, o);
    }
    __shared__ float as[8], bs[8];
    if ((c & 31) == 0) { as[c >> 5] = s; bs[c >> 5] = ss; }
    __syncthreads();
    s = 0.f; ss = 0.f;
#pragma unroll
    for (int i = 0; i < 8; i++) { s += as[i]; ss += bs[i]; }
    float mu  = s * (1.0f / H);
    float var = ss * (1.0f / H) - mu * mu;
    float inv = rsqrtf(var + 1e-5f);
    float hv = (v - mu) * inv * gm[c] + bt[c];
    us h, l;
    split1(hv, h, l);
    g_hsh[(size_t)row * H + c] = h;
    g_hsl[(size_t)row * H + c] = l;
}

__global__ __launch_bounds__(256) void lat_k(const float* __restrict__ L,
                                             const float* __restrict__ We1,
                                             const float* __restrict__ be1) {
    int g = blockIdx.x;
    __shared__ float ll[9];
    if (threadIdx.x < 9) {
        int i = threadIdx.x / 3, k = threadIdx.x % 3;
        const float* Lg = L + g * 9;
        ll[threadIdx.x] = Lg[i * 3 + 0] * Lg[k * 3 + 0] +
                          Lg[i * 3 + 1] * Lg[k * 3 + 1] +
                          Lg[i * 3 + 2] * Lg[k * 3 + 2];
    }
    __syncthreads();
    int c = threadIdx.x;
    float a = be1[c];
#pragma unroll
    for (int p = 0; p < 9; p++) a += ll[p] * We1[(512 + p) * H + c];
    g_R[g * H + c] = a;
}

// weight transpose + split: Bt[n][k] = split(W[k][n])
__global__ void tw_k(const float* __restrict__ W, int K,
                     us* __restrict__ oh, us* __restrict__ ol) {
    int idx = blockIdx.x * blockDim.x + threadIdx.x;
    if (idx >= 256 * K) return;
    int n = idx / K, k = idx % K;
    us h, l;
    split1(W[(size_t)k * 256 + n], h, l);
    oh[idx] = h;
    ol[idx] = l;
}

__global__ void split_k(const float* __restrict__ in, us* __restrict__ oh,
                        us* __restrict__ ol, int n) {
    int i = blockIdx.x * blockDim.x + threadIdx.x;
    if (i >= n) return;
    us h, l;
    split1(in[i], h, l);
    oh[i] = h;
    ol[i] = l;
}

// sinusoid embedding via angle-addition recurrence -> split bf16 planes
__global__ __launch_bounds__(256) void femb_k(const float* __restrict__ fd, int E) {
    __shared__ float fs[32 * DIS];
    const int tid = threadIdx.x;
    const int be = blockIdx.x * 32;
    if (tid < 96) {
        const int e = tid & 31;
        const int d = tid >> 5;
        const int ge = be + e;
        float x = (ge < E) ? fd[ge * 3 + d] : 0.0f;
        float th = 6.28318530717958647692f * x;
        float s1, c1;
        sincosf(th, &s1, &c1);
        int f = e;
        float sf, cf;
        sincosf(th * (float)f, &sf, &cf);
        float* rowS = fs + e * DIS + d * 64;
        float* rowC = rowS + 192;
        for (int i = 0; i < 64; ++i) {
            rowS[f] = sf;
            rowC[f] = cf;
            f++;
            float ns = sf * c1 + cf * s1;
            float nc = cf * c1 - sf * s1;
            bool wrap = (f == 64);
            sf = wrap ? 0.0f : ns;
            cf = wrap ? 1.0f : nc;
            f  = wrap ? 0 : f;
        }
    }
    __syncthreads();
    for (int i = tid; i < 32 * 48; i += 256) {
        int e = i / 48, grp = i % 48;
        if (be + e >= E) continue;
        const float* s = fs + e * DIS + grp * 8;
        us hs[8], ls[8];
#pragma unroll
        for (int c = 0; c < 8; c++) split1(s[c], hs[c], ls[c]);
        uint4 vh = make_uint4((u32)hs[0] | ((u32)hs[1] << 16), (u32)hs[2] | ((u32)hs[3] << 16),
                              (u32)hs[4] | ((u32)hs[5] << 16), (u32)hs[6] | ((u32)hs[7] << 16));
        uint4 vl = make_uint4((u32)ls[0] | ((u32)ls[1] << 16), (u32)ls[2] | ((u32)ls[3] << 16),
                              (u32)ls[4] | ((u32)ls[5] << 16), (u32)ls[6] | ((u32)ls[7] << 16));
        size_t gi = (size_t)(be + e) * 48 + grp;
        ((uint4*)g_fembh)[gi] = vh;
        ((uint4*)g_fembl)[gi] = vl;
    }
}

// ============================ HMMA GEMM ============================
// Block tile 128(M) x 128(N), 8 warps (4M x 2N), warp tile 32x64.
// bf16 hi/lo 2-term split: acc += Ah*Bh + Al*Bh + Ah*Bl (fp32 accum).
// cp.async double-buffered KC=32 chunks.
// smem per buffer: 4 planes (Ah,Al,Bh,Bl), each 128 rows x 40 halves (20 words).
// MODE 0: Cf = acc
// MODE 1: (Ch,Cl) = split(silu(acc + P[src] + Q[dst] + R[e2g]))
// MODE 2: atomicAdd(Cf[src[row]], silu(acc + bias))
// MODE 3: (Ch,Cl) = split(silu(rowScale[row]*acc + addRow + bias))
// MODE 4: Cf = addRow + silu(acc + bias)
#define PLANE 10240       // 128 * 20 words * 4B
#define BUFB  40960       // 4 planes
#define SMEM_TOTAL 81920  // 2 buffers

template <int MODE>
__global__ __launch_bounds__(256, 1) void tgemm(
    const us* __restrict__ Ah, const us* __restrict__ Al,
    const us* __restrict__ Bh, const us* __restrict__ Bl,
    int M, int K,
    const int* __restrict__ src, const int* __restrict__ dst,
    const int* __restrict__ e2g,
    const float* __restrict__ Pm, const float* __restrict__ Qm,
    const float* __restrict__ Rm,
    const float* __restrict__ bias, const float* __restrict__ rowScale,
    const float* __restrict__ addRow,
    float* __restrict__ Cf, us* __restrict__ Ch, us* __restrict__ Cl) {
    extern __shared__ char smem[];
    const u32 sb = smem_u32(smem);
    const int tid  = threadIdx.x;
    const int lane = tid & 31;
    const int wid  = tid >> 5;
    const int g = lane >> 2, q = lane & 3;
    const int row0  = blockIdx.y * 128;
    const int nbase = blockIdx.x * 128;
    const int mrow0  = (wid & 3) * 32;
    const int nwarp0 = (wid >> 2) * 64;

    float acc[2][8][4];
#pragma unroll
    for (int a = 0; a < 2; a++)
#pragma unroll
        for (int b = 0; b < 8; b++)
#pragma unroll
            for (int c = 0; c < 4; c++) acc[a][b][c] = 0.0f;

    const int nch = K >> 5;

    // issue chunk ch into buffer buf
    auto issue = [&](int ch, int buf) {
        const u32 b0 = sb + buf * BUFB;
#pragma unroll
        for (int j = 0; j < 2; j++) {
            int seg = tid + j * 256;
            int r = seg >> 2, ksg = seg & 3;
            u32 dstp = b0 + (u32)(r * 80 + ksg * 16);
            int ra = row0 + r;
            int sz = (ra < M) ? 16 : 0;
            if (ra >= M) ra = M - 1;
            size_t offa = (size_t)ra * K + ch * 32 + ksg * 8;
            cpa(dstp,             Ah + offa, sz);
            cpa(dstp + PLANE,     Al + offa, sz);
            size_t offb = (size_t)(nbase + r) * K + ch * 32 + ksg * 8;
            cpa(dstp + 2 * PLANE, Bh + offb, 16);
            cpa(dstp + 3 * PLANE, Bl + offb, 16);
        }
        cpcommit();
    };

    issue(0, 0);
    for (int ch = 0; ch < nch; ++ch) {
        bool hasnext = (ch + 1 < nch);
        if (hasnext) issue(ch + 1, (ch + 1) & 1);
        if (hasnext) cpwait<1>(); else cpwait<0>();
        __syncthreads();
        const u32 ab = sb + (ch & 1) * BUFB;
#pragma unroll
        for (int ks = 0; ks < 2; ks++) {
            u32 ah[2][4], al[2][4];
#pragma unroll
            for (int mt = 0; mt < 2; mt++) {
                u32 base = ab + (u32)((((mrow0 + mt * 16 + g) * 20) + ks * 8 + q) * 4);
                ah[mt][0] = lds32(base);
                ah[mt][1] = lds32(base + 640);
                ah[mt][2] = lds32(base + 16);
                ah[mt][3] = lds32(base + 656);
                al[mt][0] = lds32(base + PLANE);
                al[mt][1] = lds32(base + PLANE + 640);
                al[mt][2] = lds32(base + PLANE + 16);
                al[mt][3] = lds32(base + PLANE + 656);
            }
#pragma unroll
            for (int nt = 0; nt < 8; nt++) {
                u32 bbase = ab + 2 * PLANE +
                            (u32)((((nwarp0 + nt * 8 + g) * 20) + ks * 8 + q) * 4);
                u32 bh[2], bl[2];
                bh[0] = lds32(bbase);
                bh[1] = lds32(bbase + 16);
                bl[0] = lds32(bbase + PLANE);
                bl[1] = lds32(bbase + PLANE + 16);
#pragma unroll
                for (int mt = 0; mt < 2; mt++) {
                    mma16816(acc[mt][nt], ah[mt], bh);
                    mma16816(acc[mt][nt], al[mt], bh);
                    mma16816(acc[mt][nt], ah[mt], bl);
                }
            }
        }
        __syncthreads();
    }

    // ---- epilogue ----
#pragma unroll
    for (int mt = 0; mt < 2; mt++) {
#pragma unroll
        for (int h2 = 0; h2 < 2; h2++) {
            int row = row0 + mrow0 + mt * 16 + g + h2 * 8;
            if (row >= M) continue;
            int s = 0, dn = 0, gg = 0;
            float rsc = 0.0f;
            if (MODE == 1) { s = src[row]; dn = dst[row]; gg = e2g[row]; }
            if (MODE == 2) { s = src[row]; }
            if (MODE == 3) { rsc = rowScale[row]; }
#pragma unroll
            for (int nt = 0; nt < 8; nt++) {
                int col = nbase + nwarp0 + nt * 8 + 2 * q;
                float v0 = acc[mt][nt][h2 * 2 + 0];
                float v1 = acc[mt][nt][h2 * 2 + 1];
                if (MODE == 0) {
                    *(float2*)(Cf + (size_t)row * 256 + col) = make_float2(v0, v1);
                } else if (MODE == 1) {
                    float2 p2 = *(const float2*)(Pm + (size_t)s  * 256 + col);
                    float2 q2 = *(const float2*)(Qm + (size_t)dn * 256 + col);
                    float2 r2 = *(const float2*)(Rm + (size_t)gg * 256 + col);
                    float o0 = dsilu(v0 + p2.x + q2.x + r2.x);
                    float o1 = dsilu(v1 + p2.y + q2.y + r2.y);
                    us h0, l0, h1, l1;
                    split1(o0, h0, l0);
                    split1(o1, h1, l1);
                    *(u32*)(Ch + (size_t)row * 256 + col) = (u32)h0 | ((u32)h1 << 16);
                    *(u32*)(Cl + (size_t)row * 256 + col) = (u32)l0 | ((u32)l1 << 16);
                } else if (MODE == 2) {
                    float2 b2 = *(const float2*)(bias + col);
                    atomicAdd(Cf + (size_t)s * 256 + col + 0, dsilu(v0 + b2.x));
                    atomicAdd(Cf + (size_t)s * 256 + col + 1, dsilu(v1 + b2.y));
                } else if (MODE == 3) {
                    float2 b2 = *(const float2*)(bias + col);
                    float2 a2 = *(const float2*)(addRow + (size_t)row * 256 + col);
                    float o0 = dsilu(rsc * v0 + a2.x + b2.x);
                    float o1 = dsilu(rsc * v1 + a2.y + b2.y);
                    us h0, l0, h1, l1;
                    split1(o0, h0, l0);
                    split1(o1, h1, l1);
                    *(u32*)(Ch + (size_t)row * 256 + col) = (u32)h0 | ((u32)h1 << 16);
                    *(u32*)(Cl + (size_t)row * 256 + col) = (u32)l0 | ((u32)l1 << 16);
                } else {  // MODE 4
                    float2 b2 = *(const float2*)(bias + col);
                    float2 a2 = *(const float2*)(addRow + (size_t)row * 256 + col);
                    *(float2*)(Cf + (size_t)row * 256 + col) =
                        make_float2(a2.x + dsilu(v0 + b2.x), a2.y + dsilu(v1 + b2.y));
                }
            }
        }
    }
}

// ============================ host side ============================
static float *p_P, *p_Q, *p_S, *p_R, *p_sums, *p_rcnt;
static int *p_src, *p_dst, *p_e2g;
static us *p_hsh, *p_hsl, *p_fembh, *p_fembl, *p_e1h, *p_e1l;
static us *p_sumh, *p_suml, *p_t1h, *p_t1l;
static us *p_wPh, *p_wPl, *p_wQh, *p_wQl, *p_wSh, *p_wSl, *p_wFh, *p_wFl;
static us *p_w2h, *p_w2l, *p_wNh, *p_wNl, *p_wOh, *p_wOl;
static bool g_init = false;

static void init_ptrs() {
    if (g_init) return;
    g_init = true;
    cudaGetSymbolAddress((void**)&p_P, g_P);
    cudaGetSymbolAddress((void**)&p_Q, g_Q);
    cudaGetSymbolAddress((void**)&p_S, g_S);
    cudaGetSymbolAddress((void**)&p_R, g_R);
    cudaGetSymbolAddress((void**)&p_sums, g_sums);
    cudaGetSymbolAddress((void**)&p_rcnt, g_rcnt);
    cudaGetSymbolAddress((void**)&p_src, g_src);
    cudaGetSymbolAddress((void**)&p_dst, g_dst);
    cudaGetSymbolAddress((void**)&p_e2g, g_e2g);
    cudaGetSymbolAddress((void**)&p_hsh, g_hsh);
    cudaGetSymbolAddress((void**)&p_hsl, g_hsl);
    cudaGetSymbolAddress((void**)&p_fembh, g_fembh);
    cudaGetSymbolAddress((void**)&p_fembl, g_fembl);
    cudaGetSymbolAddress((void**)&p_e1h, g_e1h);
    cudaGetSymbolAddress((void**)&p_e1l, g_e1l);
    cudaGetSymbolAddress((void**)&p_sumh, g_sumh);
    cudaGetSymbolAddress((void**)&p_suml, g_suml);
    cudaGetSymbolAddress((void**)&p_t1h, g_t1h);
    cudaGetSymbolAddress((void**)&p_t1l, g_t1l);
    cudaGetSymbolAddress((void**)&p_wPh, g_wPh);
    cudaGetSymbolAddress((void**)&p_wPl, g_wPl);
    cudaGetSymbolAddress((void**)&p_wQh, g_wQh);
    cudaGetSymbolAddress((void**)&p_wQl, g_wQl);
    cudaGetSymbolAddress((void**)&p_wSh, g_wSh);
    cudaGetSymbolAddress((void**)&p_wSl, g_wSl);
    cudaGetSymbolAddress((void**)&p_wFh, g_wFh);
    cudaGetSymbolAddress((void**)&p_wFl, g_wFl);
    cudaGetSymbolAddress((void**)&p_w2h, g_w2h);
    cudaGetSymbolAddress((void**)&p_w2l, g_w2l);
    cudaGetSymbolAddress((void**)&p_wNh, g_wNh);
    cudaGetSymbolAddress((void**)&p_wNl, g_wNl);
    cudaGetSymbolAddress((void**)&p_wOh, g_wOh);
    cudaGetSymbolAddress((void**)&p_wOl, g_wOl);
    cudaFuncSetAttribute(tgemm<0>, cudaFuncAttributeMaxDynamicSharedMemorySize, SMEM_TOTAL);
    cudaFuncSetAttribute(tgemm<1>, cudaFuncAttributeMaxDynamicSharedMemorySize, SMEM_TOTAL);
    cudaFuncSetAttribute(tgemm<2>, cudaFuncAttributeMaxDynamicSharedMemorySize, SMEM_TOTAL);
    cudaFuncSetAttribute(tgemm<3>, cudaFuncAttributeMaxDynamicSharedMemorySize, SMEM_TOTAL);
    cudaFuncSetAttribute(tgemm<4>, cudaFuncAttributeMaxDynamicSharedMemorySize, SMEM_TOTAL);
}
namespace {
struct Boot {
    Boot() { init_ptrs(); }
};
static Boot boot_;
}  // namespace

extern "C" void kernel_launch(void* const* d_in, const int* in_sizes, int n_in,
                              void* d_out, int out_size) {
    init_ptrs();
    const float* nf  = (const float*)d_in[0];
    const float* lat = (const float*)d_in[1];
    const void*  eix = d_in[2];
    const void*  e2g = d_in[3];
    const float* fd  = (const float*)d_in[4];
    const float* gam = (const float*)d_in[6];
    const float* bet = (const float*)d_in[7];
    const float* We1 = (const float*)d_in[8];
    const float* be1 = (const float*)d_in[9];
    const float* We2 = (const float*)d_in[10];
    const float* be2 = (const float*)d_in[11];
    const float* Wn1 = (const float*)d_in[12];
    const float* bn1 = (const float*)d_in[13];
    const float* Wn2 = (const float*)d_in[14];
    const float* bn2 = (const float*)d_in[15];
    float* out = (float*)d_out;

    const int Nn = in_sizes[0] / H;
    const int Gn = in_sizes[1] / 9;
    const int E  = in_sizes[4] / 3;
    const dim3 gN(2, (Nn + 127) / 128);
    const dim3 gE(2, (E + 127) / 128);

    detect_k<<<1, 256>>>(eix, E);
    zero_k<<<(Nn * H + 255) / 256, 256>>>(Nn);
    convert_k<<<(E + 255) / 256, 256>>>(eix, e2g, E);
    ln_k<<<Nn, 256>>>(nf, gam, bet);
    lat_k<<<Gn, 256>>>(lat, We1, be1);
    rcnt_k<<<(Nn + 255) / 256, 256>>>(Nn);

    const int twg = (256 * 256 + 255) / 256;
    tw_k<<<twg, 256>>>(We1, 256, p_wPh, p_wPl);
    tw_k<<<twg, 256>>>(We1 + 256 * H, 256, p_wQh, p_wQl);
    tw_k<<<(256 * 384 + 255) / 256, 256>>>(We1 + 521 * H, 384, p_wFh, p_wFl);
    tw_k<<<twg, 256>>>(We2, 256, p_w2h, p_w2l);
    tw_k<<<twg, 256>>>(Wn1, 256, p_wSh, p_wSl);
    tw_k<<<twg, 256>>>(Wn1 + 256 * H, 256, p_wNh, p_wNl);
    tw_k<<<twg, 256>>>(Wn2, 256, p_wOh, p_wOl);

    femb_k<<<(E + 31) / 32, 256>>>(fd, E);

    // node precomputes: P = h@We1a, Q = h@We1b, S = h@Wn1a
    tgemm<0><<<gN, 256, SMEM_TOTAL>>>(p_hsh, p_hsl, p_wPh, p_wPl, Nn, 256,
                                      0, 0, 0, 0, 0, 0, 0, 0, 0, p_P, 0, 0);
    tgemm<0><<<gN, 256, SMEM_TOTAL>>>(p_hsh, p_hsl, p_wQh, p_wQl, Nn, 256,
                                      0, 0, 0, 0, 0, 0, 0, 0, 0, p_Q, 0, 0);
    tgemm<0><<<gN, 256, SMEM_TOTAL>>>(p_hsh, p_hsl, p_wSh, p_wSl, Nn, 256,
                                      0, 0, 0, 0, 0, 0, 0, 0, 0, p_S, 0, 0);

    // edge layer 1: e1 = silu(femb@Wf + P[src] + Q[dst] + R[e2g]) -> split bf16
    tgemm<1><<<gE, 256, SMEM_TOTAL>>>(p_fembh, p_fembl, p_wFh, p_wFl, E, 384,
                                      p_src, p_dst, p_e2g, p_P, p_Q, p_R,
                                      0, 0, 0, 0, p_e1h, p_e1l);

    // edge layer 2 + scatter: sums[src] += silu(e1@We2 + be2)
    tgemm<2><<<gE, 256, SMEM_TOTAL>>>(p_e1h, p_e1l, p_w2h, p_w2l, E, 256,
                                      p_src, 0, 0, 0, 0, 0,
                                      be2, 0, 0, p_sums, 0, 0);

    split_k<<<(Nn * H + 255) / 256, 256>>>(p_sums, p_sumh, p_suml, Nn * H);

    // node layer 1: t1 = silu(rcnt*(sums@Wn1b) + S + bn1) -> split bf16
    tgemm<3><<<gN, 256, SMEM_TOTAL>>>(p_sumh, p_suml, p_wNh, p_wNl, Nn, 256,
                                      0, 0, 0, 0, 0, 0,
                                      bn1, p_rcnt, p_S, 0, p_t1h, p_t1l);

    // node layer 2 + residual: out = nf + silu(t1@Wn2 + bn2)
    tgemm<4><<<gN, 256, SMEM_TOTAL>>>(p_t1h, p_t1l, p_wOh, p_wOl, Nn, 256,
                                      0, 0, 0, 0, 0, 0,
                                      bn2, 0, nf, out, 0, 0);
}

// round 7
// speedup vs baseline: 2.3428x; 1.0361x over previous
#include <cuda_runtime.h>
#include <cuda_bf16.h>
#include <cstdint>

#define H 256
#define NMAX 20000
#define EMAX 320000
#define GMAX 1000
#define DIS 384

typedef unsigned int u32;
typedef unsigned short us;

// ============================ helpers ============================
__device__ __forceinline__ u32 smem_u32(const void* p) {
    u32 a;
    asm("{ .reg .u64 t; cvta.to.shared.u64 t, %1; cvt.u32.u64 %0, t; }" : "=r"(a) : "l"(p));
    return a;
}
__device__ __forceinline__ void cpa(u32 dst, const void* src, int sz) {
    asm volatile("cp.async.cg.shared.global [%0], [%1], 16, %2;"
                 :: "r"(dst), "l"(src), "r"(sz) : "memory");
}
__device__ __forceinline__ void cpcommit() {
    asm volatile("cp.async.commit_group;" ::: "memory");
}
template <int N>
__device__ __forceinline__ void cpwait() {
    asm volatile("cp.async.wait_group %0;" :: "n"(N) : "memory");
}
// ldmatrix x4: 4 8x8 b16 matrices (arch-neutral, sm_75+)
__device__ __forceinline__ void ldmx4(u32* r, u32 addr) {
    asm volatile("ldmatrix.sync.aligned.m8n8.x4.shared.b16 {%0,%1,%2,%3}, [%4];"
                 : "=r"(r[0]), "=r"(r[1]), "=r"(r[2]), "=r"(r[3]) : "r"(addr));
}
// m16n8k16 bf16 mma, fp32 accum (arch-neutral HMMA path)
__device__ __forceinline__ void mma16816(float* c, const u32* a, const u32* b) {
    asm volatile(
        "mma.sync.aligned.m16n8k16.row.col.f32.bf16.bf16.f32 "
        "{%0,%1,%2,%3},{%4,%5,%6,%7},{%8,%9},{%0,%1,%2,%3};"
        : "+f"(c[0]), "+f"(c[1]), "+f"(c[2]), "+f"(c[3])
        : "r"(a[0]), "r"(a[1]), "r"(a[2]), "r"(a[3]), "r"(b[0]), "r"(b[1]));
}
__device__ __forceinline__ float dsilu(float x) {
    return __fdividef(x, 1.0f + __expf(-x));
}
__device__ __forceinline__ void split1(float v, us& h, us& l) {
    __nv_bfloat16 bh = __float2bfloat16(v);
    float hv = __bfloat162float(bh);
    __nv_bfloat16 bl = __float2bfloat16(v - hv);
    h = *reinterpret_cast<us*>(&bh);
    l = *reinterpret_cast<us*>(&bl);
}

// ============================ device scratch ============================
__device__ int g_is64;
__device__ int g_src[EMAX];
__device__ int g_dst[EMAX];
__device__ int g_e2g[EMAX];
__device__ float g_PQS[(size_t)NMAX * 768];  // P | Q | S interleaved per row
__device__ float g_R[GMAX * H];
__device__ float g_sums[NMAX * H];
__device__ float g_cnt[NMAX];
__device__ float g_rcnt[NMAX];
__device__ us g_hsh[NMAX * H];
__device__ us g_hsl[NMAX * H];
__device__ us g_fembh[(size_t)EMAX * DIS];
__device__ us g_fembl[(size_t)EMAX * DIS];
__device__ us g_e1h[(size_t)EMAX * H];
__device__ us g_e1l[(size_t)EMAX * H];
__device__ us g_sumh[NMAX * H];
__device__ us g_suml[NMAX * H];
__device__ us g_t1h[NMAX * H];
__device__ us g_t1l[NMAX * H];
__device__ us g_wPQSh[768 * H], g_wPQSl[768 * H];  // merged P/Q/S weights^T
__device__ us g_wFh[H * DIS],  g_wFl[H * DIS];
__device__ us g_w2h[H * H],    g_w2l[H * H];
__device__ us g_wNh[H * H],    g_wNl[H * H];
__device__ us g_wOh[H * H],    g_wOl[H * H];

// ============================ small kernels ============================
__global__ void detect_k(const void* eidx, int E) {
    __shared__ int any;
    if (threadIdx.x == 0) any = 0;
    __syncthreads();
    const int* w = (const int*)eidx;
    int lim = 2048 < (E - 1) ? 2048 : (E - 1);
    for (int i = threadIdx.x; i < lim; i += blockDim.x)
        if (w[2 * i + 1] != 0) any = 1;
    __syncthreads();
    if (threadIdx.x == 0) g_is64 = (any == 0) ? 1 : 0;
}

__global__ void convert_k(const void* eidx, const void* e2g, int E) {
    int i = blockIdx.x * blockDim.x + threadIdx.x;
    if (i >= E) return;
    int s;
    if (g_is64) {
        const long long* p = (const long long*)eidx;
        const long long* q = (const long long*)e2g;
        s = (int)p[i];
        g_dst[i] = (int)p[(size_t)E + i];
        g_e2g[i] = (int)q[i];
    } else {
        const int* p = (const int*)eidx;
        const int* q = (const int*)e2g;
        s = p[i];
        g_dst[i] = p[E + i];
        g_e2g[i] = q[i];
    }
    g_src[i] = s;
    atomicAdd(&g_cnt[s], 1.0f);
}

__global__ void zero_k(int Nn) {
    int i = blockIdx.x * blockDim.x + threadIdx.x;
    if (i < Nn * H) g_sums[i] = 0.0f;
    if (i < Nn) g_cnt[i] = 0.0f;
}

__global__ void rcnt_k(int Nn) {
    int i = blockIdx.x * blockDim.x + threadIdx.x;
    if (i < Nn) g_rcnt[i] = 1.0f / fmaxf(g_cnt[i], 1.0f);
}

__global__ __launch_bounds__(256) void ln_k(const float* __restrict__ x,
                                            const float* __restrict__ gm,
                                            const float* __restrict__ bt) {
    int row = blockIdx.x;
    int c = threadIdx.x;
    float v = x[(size_t)row * H + c];
    float s = v, ss = v * v;
#pragma unroll
    for (int o = 16; o; o >>= 1) {
        s  += __shfl_xor_sync(0xffffffffu, s, o);
        ss += __shfl_xor_sync(0xffffffffu, ss, o);
    }
    __shared__ float as[8], bs[8];
    if ((c & 31) == 0) { as[c >> 5] = s; bs[c >> 5] = ss; }
    __syncthreads();
    s = 0.f; ss = 0.f;
#pragma unroll
    for (int i = 0; i < 8; i++) { s += as[i]; ss += bs[i]; }
    float mu  = s * (1.0f / H);
    float var = ss * (1.0f / H) - mu * mu;
    float inv = rsqrtf(var + 1e-5f);
    float hv = (v - mu) * inv * gm[c] + bt[c];
    us h, l;
    split1(hv, h, l);
    g_hsh[(size_t)row * H + c] = h;
    g_hsl[(size_t)row * H + c] = l;
}

__global__ __launch_bounds__(256) void lat_k(const float* __restrict__ L,
                                             const float* __restrict__ We1,
                                             const float* __restrict__ be1) {
    int g = blockIdx.x;
    __shared__ float ll[9];
    if (threadIdx.x < 9) {
        int i = threadIdx.x / 3, k = threadIdx.x % 3;
        const float* Lg = L + g * 9;
        ll[threadIdx.x] = Lg[i * 3 + 0] * Lg[k * 3 + 0] +
                          Lg[i * 3 + 1] * Lg[k * 3 + 1] +
                          Lg[i * 3 + 2] * Lg[k * 3 + 2];
    }
    __syncthreads();
    int c = threadIdx.x;
    float a = be1[c];
#pragma unroll
    for (int p = 0; p < 9; p++) a += ll[p] * We1[(512 + p) * H + c];
    g_R[g * H + c] = a;
}

// weight transpose + split: Bt[n][k] = split(W[k][n])
__global__ void tw_k(const float* __restrict__ W, int K,
                     us* __restrict__ oh, us* __restrict__ ol) {
    int idx = blockIdx.x * blockDim.x + threadIdx.x;
    if (idx >= 256 * K) return;
    int n = idx / K, k = idx % K;
    us h, l;
    split1(W[(size_t)k * 256 + n], h, l);
    oh[idx] = h;
    ol[idx] = l;
}

__global__ void split_k(const float* __restrict__ in, us* __restrict__ oh,
                        us* __restrict__ ol, int n) {
    int i = blockIdx.x * blockDim.x + threadIdx.x;
    if (i >= n) return;
    us h, l;
    split1(in[i], h, l);
    oh[i] = h;
    ol[i] = l;
}

// sinusoid embedding via angle-addition recurrence -> split bf16 planes
__global__ __launch_bounds__(256) void femb_k(const float* __restrict__ fd, int E) {
    __shared__ float fs[32 * DIS];
    const int tid = threadIdx.x;
    const int be = blockIdx.x * 32;
    if (tid < 96) {
        const int e = tid & 31;
        const int d = tid >> 5;
        const int ge = be + e;
        float x = (ge < E) ? fd[ge * 3 + d] : 0.0f;
        float th = 6.28318530717958647692f * x;
        float s1, c1;
        sincosf(th, &s1, &c1);
        int f = e;
        float sf, cf;
        sincosf(th * (float)f, &sf, &cf);
        float* rowS = fs + e * DIS + d * 64;
        float* rowC = rowS + 192;
        for (int i = 0; i < 64; ++i) {
            rowS[f] = sf;
            rowC[f] = cf;
            f++;
            float ns = sf * c1 + cf * s1;
            float nc = cf * c1 - sf * s1;
            bool wrap = (f == 64);
            sf = wrap ? 0.0f : ns;
            cf = wrap ? 1.0f : nc;
            f  = wrap ? 0 : f;
        }
    }
    __syncthreads();
    for (int i = tid; i < 32 * 48; i += 256) {
        int e = i / 48, grp = i % 48;
        if (be + e >= E) continue;
        const float* s = fs + e * DIS + grp * 8;
        us hs[8], ls[8];
#pragma unroll
        for (int c = 0; c < 8; c++) split1(s[c], hs[c], ls[c]);
        uint4 vh = make_uint4((u32)hs[0] | ((u32)hs[1] << 16), (u32)hs[2] | ((u32)hs[3] << 16),
                              (u32)hs[4] | ((u32)hs[5] << 16), (u32)hs[6] | ((u32)hs[7] << 16));
        uint4 vl = make_uint4((u32)ls[0] | ((u32)ls[1] << 16), (u32)ls[2] | ((u32)ls[3] << 16),
                              (u32)ls[4] | ((u32)ls[5] << 16), (u32)ls[6] | ((u32)ls[7] << 16));
        size_t gi = (size_t)(be + e) * 48 + grp;
        ((uint4*)g_fembh)[gi] = vh;
        ((uint4*)g_fembl)[gi] = vl;
    }
}

// ============================ HMMA GEMM (ldmatrix) ============================
// Block tile 128(M) x 128(N), 8 warps (4M x 2N), warp tile 32x64.
// bf16 hi/lo 2-term split: acc += Ah*Bh + Al*Bh + Ah*Bl (fp32 accum).
// cp.async double-buffered KC=32 chunks; fragments via ldmatrix.x4.
// smem per buffer: 4 planes (Ah,Al,Bh,Bl), each 128 rows x 20 words (80B stride
// -> ldmatrix 8-row phases hit all 32 banks).
// MODE 0: Cf[row*ldx+col] = acc
// MODE 1: (Ch,Cl) = split(silu(acc + P[src] + Q[dst] + R[e2g]))  (P/Q stride ldx)
// MODE 2: atomicAdd(Cf[src[row]], silu(acc + bias))
// MODE 3: (Ch,Cl) = split(silu(rowScale[row]*acc + addRow + bias))  (addRow stride ldx)
// MODE 4: Cf = addRow + silu(acc + bias)
#define PLANE 10240       // 128 * 20 words * 4B
#define BUFB  40960       // 4 planes
#define SMEM_TOTAL 81920  // 2 buffers

template <int MODE>
__global__ __launch_bounds__(256, 1) void tgemm(
    const us* __restrict__ Ah, const us* __restrict__ Al,
    const us* __restrict__ Bh, const us* __restrict__ Bl,
    int M, int K, int ldx,
    const int* __restrict__ src, const int* __restrict__ dst,
    const int* __restrict__ e2g,
    const float* __restrict__ Pm, const float* __restrict__ Qm,
    const float* __restrict__ Rm,
    const float* __restrict__ bias, const float* __restrict__ rowScale,
    const float* __restrict__ addRow,
    float* __restrict__ Cf, us* __restrict__ Ch, us* __restrict__ Cl) {
    extern __shared__ char smem[];
    const u32 sb = smem_u32(smem);
    const int tid  = threadIdx.x;
    const int lane = tid & 31;
    const int wid  = tid >> 5;
    const int g = lane >> 2, q = lane & 3;
    const int row0  = blockIdx.y * 128;
    const int nbase = blockIdx.x * 128;
    const int mrow0  = (wid & 3) * 32;
    const int nwarp0 = (wid >> 2) * 64;

    // ldmatrix per-thread address offsets (within a buffer)
    const int rowin = lane & 7;
    const int msel  = lane >> 3;
    u32 offA[2][2];  // [plane][mt]
#pragma unroll
    for (int pl = 0; pl < 2; pl++)
#pragma unroll
        for (int mt = 0; mt < 2; mt++)
            offA[pl][mt] = (u32)(pl * PLANE +
                                 (mrow0 + mt * 16 + rowin + (msel & 1) * 8) * 80 +
                                 (msel >> 1) * 16);
    u32 offB[2];  // [plane], nt2=0
#pragma unroll
    for (int pl = 0; pl < 2; pl++)
        offB[pl] = (u32)((2 + pl) * PLANE +
                         (nwarp0 + (msel >> 1) * 8 + rowin) * 80 +
                         (msel & 1) * 16);

    float acc[2][8][4];
#pragma unroll
    for (int a = 0; a < 2; a++)
#pragma unroll
        for (int b = 0; b < 8; b++)
#pragma unroll
            for (int c = 0; c < 4; c++) acc[a][b][c] = 0.0f;

    const int nch = K >> 5;

    auto issue = [&](int ch, int buf) {
        const u32 b0 = sb + buf * BUFB;
#pragma unroll
        for (int j = 0; j < 2; j++) {
            int seg = tid + j * 256;
            int r = seg >> 2, ksg = seg & 3;
            u32 dstp = b0 + (u32)(r * 80 + ksg * 16);
            int ra = row0 + r;
            int sz = (ra < M) ? 16 : 0;
            if (ra >= M) ra = M - 1;
            size_t offa = (size_t)ra * K + ch * 32 + ksg * 8;
            cpa(dstp,             Ah + offa, sz);
            cpa(dstp + PLANE,     Al + offa, sz);
            size_t offb = (size_t)(nbase + r) * K + ch * 32 + ksg * 8;
            cpa(dstp + 2 * PLANE, Bh + offb, 16);
            cpa(dstp + 3 * PLANE, Bl + offb, 16);
        }
        cpcommit();
    };

    issue(0, 0);
    for (int ch = 0; ch < nch; ++ch) {
        bool hasnext = (ch + 1 < nch);
        if (hasnext) issue(ch + 1, (ch + 1) & 1);
        if (hasnext) cpwait<1>(); else cpwait<0>();
        __syncthreads();
        const u32 ab = sb + (ch & 1) * BUFB;
#pragma unroll
        for (int ks = 0; ks < 2; ks++) {
            u32 afr[2][2][4];  // [mt][plane]
#pragma unroll
            for (int mt = 0; mt < 2; mt++) {
                ldmx4(afr[mt][0], ab + offA[0][mt] + ks * 32);
                ldmx4(afr[mt][1], ab + offA[1][mt] + ks * 32);
            }
#pragma unroll
            for (int nt2 = 0; nt2 < 4; nt2++) {
                u32 bh[4], bl[4];
                ldmx4(bh, ab + offB[0] + nt2 * 1280 + ks * 32);
                ldmx4(bl, ab + offB[1] + nt2 * 1280 + ks * 32);
#pragma unroll
                for (int hv = 0; hv < 2; hv++) {
                    const int nt = nt2 * 2 + hv;
#pragma unroll
                    for (int mt = 0; mt < 2; mt++) {
                        mma16816(acc[mt][nt], afr[mt][0], bh + 2 * hv);
                        mma16816(acc[mt][nt], afr[mt][1], bh + 2 * hv);
                        mma16816(acc[mt][nt], afr[mt][0], bl + 2 * hv);
                    }
                }
            }
        }
        __syncthreads();
    }

    // ---- epilogue ----
#pragma unroll
    for (int mt = 0; mt < 2; mt++) {
#pragma unroll
        for (int h2 = 0; h2 < 2; h2++) {
            int row = row0 + mrow0 + mt * 16 + g + h2 * 8;
            if (row >= M) continue;
            int s = 0, dn = 0, gg = 0;
            float rsc = 0.0f;
            if (MODE == 1) { s = src[row]; dn = dst[row]; gg = e2g[row]; }
            if (MODE == 2) { s = src[row]; }
            if (MODE == 3) { rsc = rowScale[row]; }
#pragma unroll
            for (int nt = 0; nt < 8; nt++) {
                int col = nbase + nwarp0 + nt * 8 + 2 * q;
                float v0 = acc[mt][nt][h2 * 2 + 0];
                float v1 = acc[mt][nt][h2 * 2 + 1];
                if (MODE == 0) {
                    *(float2*)(Cf + (size_t)row * ldx + col) = make_float2(v0, v1);
                } else if (MODE == 1) {
                    float2 p2 = *(const float2*)(Pm + (size_t)s  * ldx + col);
                    float2 q2 = *(const float2*)(Qm + (size_t)dn * ldx + col);
                    float2 r2 = *(const float2*)(Rm + (size_t)gg * 256 + col);
                    float o0 = dsilu(v0 + p2.x + q2.x + r2.x);
                    float o1 = dsilu(v1 + p2.y + q2.y + r2.y);
                    us h0, l0, h1, l1;
                    split1(o0, h0, l0);
                    split1(o1, h1, l1);
                    *(u32*)(Ch + (size_t)row * 256 + col) = (u32)h0 | ((u32)h1 << 16);
                    *(u32*)(Cl + (size_t)row * 256 + col) = (u32)l0 | ((u32)l1 << 16);
                } else if (MODE == 2) {
                    float2 b2 = *(const float2*)(bias + col);
                    atomicAdd(Cf + (size_t)s * 256 + col + 0, dsilu(v0 + b2.x));
                    atomicAdd(Cf + (size_t)s * 256 + col + 1, dsilu(v1 + b2.y));
                } else if (MODE == 3) {
                    float2 b2 = *(const float2*)(bias + col);
                    float2 a2 = *(const float2*)(addRow + (size_t)row * ldx + col);
                    float o0 = dsilu(rsc * v0 + a2.x + b2.x);
                    float o1 = dsilu(rsc * v1 + a2.y + b2.y);
                    us h0, l0, h1, l1;
                    split1(o0, h0, l0);
                    split1(o1, h1, l1);
                    *(u32*)(Ch + (size_t)row * 256 + col) = (u32)h0 | ((u32)h1 << 16);
                    *(u32*)(Cl + (size_t)row * 256 + col) = (u32)l0 | ((u32)l1 << 16);
                } else {  // MODE 4
                    float2 b2 = *(const float2*)(bias + col);
                    float2 a2 = *(const float2*)(addRow + (size_t)row * 256 + col);
                    *(float2*)(Cf + (size_t)row * 256 + col) =
                        make_float2(a2.x + dsilu(v0 + b2.x), a2.y + dsilu(v1 + b2.y));
                }
            }
        }
    }
}

// ============================ host side ============================
static float *p_PQS, *p_R, *p_sums, *p_rcnt;
static int *p_src, *p_dst, *p_e2g;
static us *p_hsh, *p_hsl, *p_fembh, *p_fembl, *p_e1h, *p_e1l;
static us *p_sumh, *p_suml, *p_t1h, *p_t1l;
static us *p_wPQSh, *p_wPQSl, *p_wFh, *p_wFl;
static us *p_w2h, *p_w2l, *p_wNh, *p_wNl, *p_wOh, *p_wOl;
static bool g_init = false;

static void init_ptrs() {
    if (g_init) return;
    g_init = true;
    cudaGetSymbolAddress((void**)&p_PQS, g_PQS);
    cudaGetSymbolAddress((void**)&p_R, g_R);
    cudaGetSymbolAddress((void**)&p_sums, g_sums);
    cudaGetSymbolAddress((void**)&p_rcnt, g_rcnt);
    cudaGetSymbolAddress((void**)&p_src, g_src);
    cudaGetSymbolAddress((void**)&p_dst, g_dst);
    cudaGetSymbolAddress((void**)&p_e2g, g_e2g);
    cudaGetSymbolAddress((void**)&p_hsh, g_hsh);
    cudaGetSymbolAddress((void**)&p_hsl, g_hsl);
    cudaGetSymbolAddress((void**)&p_fembh, g_fembh);
    cudaGetSymbolAddress((void**)&p_fembl, g_fembl);
    cudaGetSymbolAddress((void**)&p_e1h, g_e1h);
    cudaGetSymbolAddress((void**)&p_e1l, g_e1l);
    cudaGetSymbolAddress((void**)&p_sumh, g_sumh);
    cudaGetSymbolAddress((void**)&p_suml, g_suml);
    cudaGetSymbolAddress((void**)&p_t1h, g_t1h);
    cudaGetSymbolAddress((void**)&p_t1l, g_t1l);
    cudaGetSymbolAddress((void**)&p_wPQSh, g_wPQSh);
    cudaGetSymbolAddress((void**)&p_wPQSl, g_wPQSl);
    cudaGetSymbolAddress((void**)&p_wFh, g_wFh);
    cudaGetSymbolAddress((void**)&p_wFl, g_wFl);
    cudaGetSymbolAddress((void**)&p_w2h, g_w2h);
    cudaGetSymbolAddress((void**)&p_w2l, g_w2l);
    cudaGetSymbolAddress((void**)&p_wNh, g_wNh);
    cudaGetSymbolAddress((void**)&p_wNl, g_wNl);
    cudaGetSymbolAddress((void**)&p_wOh, g_wOh);
    cudaGetSymbolAddress((void**)&p_wOl, g_wOl);
    cudaFuncSetAttribute(tgemm<0>, cudaFuncAttributeMaxDynamicSharedMemorySize, SMEM_TOTAL);
    cudaFuncSetAttribute(tgemm<1>, cudaFuncAttributeMaxDynamicSharedMemorySize, SMEM_TOTAL);
    cudaFuncSetAttribute(tgemm<2>, cudaFuncAttributeMaxDynamicSharedMemorySize, SMEM_TOTAL);
    cudaFuncSetAttribute(tgemm<3>, cudaFuncAttributeMaxDynamicSharedMemorySize, SMEM_TOTAL);
    cudaFuncSetAttribute(tgemm<4>, cudaFuncAttributeMaxDynamicSharedMemorySize, SMEM_TOTAL);
}
namespace {
struct Boot {
    Boot() { init_ptrs(); }
};
static Boot boot_;
}  // namespace

extern "C" void kernel_launch(void* const* d_in, const int* in_sizes, int n_in,
                              void* d_out, int out_size) {
    init_ptrs();
    const float* nf  = (const float*)d_in[0];
    const float* lat = (const float*)d_in[1];
    const void*  eix = d_in[2];
    const void*  e2g = d_in[3];
    const float* fd  = (const float*)d_in[4];
    const float* gam = (const float*)d_in[6];
    const float* bet = (const float*)d_in[7];
    const float* We1 = (const float*)d_in[8];
    const float* be1 = (const float*)d_in[9];
    const float* We2 = (const float*)d_in[10];
    const float* be2 = (const float*)d_in[11];
    const float* Wn1 = (const float*)d_in[12];
    const float* bn1 = (const float*)d_in[13];
    const float* Wn2 = (const float*)d_in[14];
    const float* bn2 = (const float*)d_in[15];
    float* out = (float*)d_out;

    const int Nn = in_sizes[0] / H;
    const int Gn = in_sizes[1] / 9;
    const int E  = in_sizes[4] / 3;
    const dim3 gN(2, (Nn + 127) / 128);
    const dim3 gN3(6, (Nn + 127) / 128);  // merged P|Q|S, N=768
    const dim3 gE(2, (E + 127) / 128);

    detect_k<<<1, 256>>>(eix, E);
    zero_k<<<(Nn * H + 255) / 256, 256>>>(Nn);
    convert_k<<<(E + 255) / 256, 256>>>(eix, e2g, E);
    ln_k<<<Nn, 256>>>(nf, gam, bet);
    lat_k<<<Gn, 256>>>(lat, We1, be1);
    rcnt_k<<<(Nn + 255) / 256, 256>>>(Nn);

    const int twg = (256 * 256 + 255) / 256;
    tw_k<<<twg, 256>>>(We1, 256, p_wPQSh, p_wPQSl);                         // n 0..255   (P)
    tw_k<<<twg, 256>>>(We1 + 256 * H, 256, p_wPQSh + 256 * H, p_wPQSl + 256 * H);  // Q
    tw_k<<<twg, 256>>>(Wn1, 256, p_wPQSh + 512 * H, p_wPQSl + 512 * H);     // S
    tw_k<<<(256 * 384 + 255) / 256, 256>>>(We1 + 521 * H, 384, p_wFh, p_wFl);
    tw_k<<<twg, 256>>>(We2, 256, p_w2h, p_w2l);
    tw_k<<<twg, 256>>>(Wn1 + 256 * H, 256, p_wNh, p_wNl);
    tw_k<<<twg, 256>>>(Wn2, 256, p_wOh, p_wOl);

    femb_k<<<(E + 31) / 32, 256>>>(fd, E);

    // merged node precompute: PQS = h @ [We1a | We1b | Wn1a]  (N=768)
    tgemm<0><<<gN3, 256, SMEM_TOTAL>>>(p_hsh, p_hsl, p_wPQSh, p_wPQSl, Nn, 256, 768,
                                       0, 0, 0, 0, 0, 0, 0, 0, 0, p_PQS, 0, 0);

    // edge layer 1: e1 = silu(femb@Wf + P[src] + Q[dst] + R[e2g]) -> split bf16
    tgemm<1><<<gE, 256, SMEM_TOTAL>>>(p_fembh, p_fembl, p_wFh, p_wFl, E, 384, 768,
                                      p_src, p_dst, p_e2g, p_PQS, p_PQS + 256, p_R,
                                      0, 0, 0, 0, p_e1h, p_e1l);

    // edge layer 2 + scatter: sums[src] += silu(e1@We2 + be2)
    tgemm<2><<<gE, 256, SMEM_TOTAL>>>(p_e1h, p_e1l, p_w2h, p_w2l, E, 256, 256,
                                      p_src, 0, 0, 0, 0, 0,
                                      be2, 0, 0, p_sums, 0, 0);

    split_k<<<(Nn * H + 255) / 256, 256>>>(p_sums, p_sumh, p_suml, Nn * H);

    // node layer 1: t1 = silu(rcnt*(sums@Wn1b) + S + bn1) -> split bf16
    tgemm<3><<<gN, 256, SMEM_TOTAL>>>(p_sumh, p_suml, p_wNh, p_wNl, Nn, 256, 768,
                                      0, 0, 0, 0, 0, 0,
                                      bn1, p_rcnt, p_PQS + 512, 0, p_t1h, p_t1l);

    // node layer 2 + residual: out = nf + silu(t1@Wn2 + bn2)
    tgemm<4><<<gN, 256, SMEM_TOTAL>>>(p_t1h, p_t1l, p_wOh, p_wOl, Nn, 256, 256,
                                      0, 0, 0, 0, 0, 0,
                                      bn2, 0, nf, out, 0, 0);
}

// round 8
// speedup vs baseline: 3.7657x; 1.6073x over previous
#include <cuda_runtime.h>
#include <cuda_fp16.h>
#include <cstdint>

#define H 256
#define NMAX 20000
#define EMAX 320000
#define GMAX 1000
#define DIS 384

typedef unsigned int u32;
typedef unsigned short us;

// ============================ helpers ============================
__device__ __forceinline__ u32 smem_u32(const void* p) {
    u32 a;
    asm("{ .reg .u64 t; cvta.to.shared.u64 t, %1; cvt.u32.u64 %0, t; }" : "=r"(a) : "l"(p));
    return a;
}
__device__ __forceinline__ void cpa(u32 dst, const void* src, int sz) {
    asm volatile("cp.async.cg.shared.global [%0], [%1], 16, %2;"
                 :: "r"(dst), "l"(src), "r"(sz) : "memory");
}
__device__ __forceinline__ void cpcommit() {
    asm volatile("cp.async.commit_group;" ::: "memory");
}
template <int N>
__device__ __forceinline__ void cpwait() {
    asm volatile("cp.async.wait_group %0;" :: "n"(N) : "memory");
}
__device__ __forceinline__ void ldmx4(u32* r, u32 addr) {
    asm volatile("ldmatrix.sync.aligned.m8n8.x4.shared.b16 {%0,%1,%2,%3}, [%4];"
                 : "=r"(r[0]), "=r"(r[1]), "=r"(r[2]), "=r"(r[3]) : "r"(addr));
}
// m16n8k16 fp16 mma, fp32 accum (arch-neutral HMMA path)
__device__ __forceinline__ void mma16816(float* c, const u32* a, const u32* b) {
    asm volatile(
        "mma.sync.aligned.m16n8k16.row.col.f32.f16.f16.f32 "
        "{%0,%1,%2,%3},{%4,%5,%6,%7},{%8,%9},{%0,%1,%2,%3};"
        : "+f"(c[0]), "+f"(c[1]), "+f"(c[2]), "+f"(c[3])
        : "r"(a[0]), "r"(a[1]), "r"(a[2]), "r"(a[3]), "r"(b[0]), "r"(b[1]));
}
__device__ __forceinline__ float dsilu(float x) {
    return __fdividef(x, 1.0f + __expf(-x));
}
__device__ __forceinline__ us cvt1(float v) {
    __half h = __float2half(v);
    return *reinterpret_cast<us*>(&h);
}
// weight split: w = hi(fp16) + lo(fp16)
__device__ __forceinline__ void wsplit(float v, us& h, us& l) {
    __half hh = __float2half(v);
    float hv = __half2float(hh);
    __half ll = __float2half(v - hv);
    h = *reinterpret_cast<us*>(&hh);
    l = *reinterpret_cast<us*>(&ll);
}

// ============================ device scratch ============================
__device__ int g_is64;
__device__ int g_src[EMAX];
__device__ int g_dst[EMAX];
__device__ int g_e2g[EMAX];
__device__ float g_PQS[(size_t)NMAX * 768];  // P | Q | S per row
__device__ float g_R[GMAX * H];
__device__ float g_sums[NMAX * H];
__device__ float g_cnt[NMAX];
__device__ float g_rcnt[NMAX];
// fp16 activations (single plane each)
__device__ us g_hs[NMAX * H];
__device__ us g_femb[(size_t)EMAX * DIS];
__device__ us g_e1[(size_t)EMAX * H];
__device__ us g_sum16[NMAX * H];
__device__ us g_t1[NMAX * H];
// fp16 hi/lo transposed weights Bt[n][k]
__device__ us g_wPQSh[768 * H], g_wPQSl[768 * H];
__device__ us g_wFh[H * DIS],  g_wFl[H * DIS];
__device__ us g_w2h[H * H],    g_w2l[H * H];
__device__ us g_wNh[H * H],    g_wNl[H * H];
__device__ us g_wOh[H * H],    g_wOl[H * H];

// ============================ small kernels ============================
__global__ void detect_k(const void* eidx, int E) {
    __shared__ int any;
    if (threadIdx.x == 0) any = 0;
    __syncthreads();
    const int* w = (const int*)eidx;
    int lim = 2048 < (E - 1) ? 2048 : (E - 1);
    for (int i = threadIdx.x; i < lim; i += blockDim.x)
        if (w[2 * i + 1] != 0) any = 1;
    __syncthreads();
    if (threadIdx.x == 0) g_is64 = (any == 0) ? 1 : 0;
}

__global__ void convert_k(const void* eidx, const void* e2g, int E) {
    int i = blockIdx.x * blockDim.x + threadIdx.x;
    if (i >= E) return;
    int s;
    if (g_is64) {
        const long long* p = (const long long*)eidx;
        const long long* q = (const long long*)e2g;
        s = (int)p[i];
        g_dst[i] = (int)p[(size_t)E + i];
        g_e2g[i] = (int)q[i];
    } else {
        const int* p = (const int*)eidx;
        const int* q = (const int*)e2g;
        s = p[i];
        g_dst[i] = p[E + i];
        g_e2g[i] = q[i];
    }
    g_src[i] = s;
    atomicAdd(&g_cnt[s], 1.0f);
}

__global__ void zero_k(int Nn) {
    int i = blockIdx.x * blockDim.x + threadIdx.x;
    if (i < Nn * H) g_sums[i] = 0.0f;
    if (i < Nn) g_cnt[i] = 0.0f;
}

__global__ void rcnt_k(int Nn) {
    int i = blockIdx.x * blockDim.x + threadIdx.x;
    if (i < Nn) g_rcnt[i] = 1.0f / fmaxf(g_cnt[i], 1.0f);
}

__global__ __launch_bounds__(256) void ln_k(const float* __restrict__ x,
                                            const float* __restrict__ gm,
                                            const float* __restrict__ bt) {
    int row = blockIdx.x;
    int c = threadIdx.x;
    float v = x[(size_t)row * H + c];
    float s = v, ss = v * v;
#pragma unroll
    for (int o = 16; o; o >>= 1) {
        s  += __shfl_xor_sync(0xffffffffu, s, o);
        ss += __shfl_xor_sync(0xffffffffu, ss, o);
    }
    __shared__ float as[8], bs[8];
    if ((c & 31) == 0) { as[c >> 5] = s; bs[c >> 5] = ss; }
    __syncthreads();
    s = 0.f; ss = 0.f;
#pragma unroll
    for (int i = 0; i < 8; i++) { s += as[i]; ss += bs[i]; }
    float mu  = s * (1.0f / H);
    float var = ss * (1.0f / H) - mu * mu;
    float inv = rsqrtf(var + 1e-5f);
    g_hs[(size_t)row * H + c] = cvt1((v - mu) * inv * gm[c] + bt[c]);
}

__global__ __launch_bounds__(256) void lat_k(const float* __restrict__ L,
                                             const float* __restrict__ We1,
                                             const float* __restrict__ be1) {
    int g = blockIdx.x;
    __shared__ float ll[9];
    if (threadIdx.x < 9) {
        int i = threadIdx.x / 3, k = threadIdx.x % 3;
        const float* Lg = L + g * 9;
        ll[threadIdx.x] = Lg[i * 3 + 0] * Lg[k * 3 + 0] +
                          Lg[i * 3 + 1] * Lg[k * 3 + 1] +
                          Lg[i * 3 + 2] * Lg[k * 3 + 2];
    }
    __syncthreads();
    int c = threadIdx.x;
    float a = be1[c];
#pragma unroll
    for (int p = 0; p < 9; p++) a += ll[p] * We1[(512 + p) * H + c];
    g_R[g * H + c] = a;
}

// weight transpose + fp16 hi/lo split: Bt[n][k] = split(W[k][n])
__global__ void tw_k(const float* __restrict__ W, int K,
                     us* __restrict__ oh, us* __restrict__ ol) {
    int idx = blockIdx.x * blockDim.x + threadIdx.x;
    if (idx >= 256 * K) return;
    int n = idx / K, k = idx % K;
    us h, l;
    wsplit(W[(size_t)k * 256 + n], h, l);
    oh[idx] = h;
    ol[idx] = l;
}

__global__ void cvt_k(const float* __restrict__ in, us* __restrict__ o, int n) {
    int i = blockIdx.x * blockDim.x + threadIdx.x;
    if (i < n) o[i] = cvt1(in[i]);
}

// sinusoid embedding via angle-addition recurrence -> fp16
__global__ __launch_bounds__(256) void femb_k(const float* __restrict__ fd, int E) {
    __shared__ float fs[32 * DIS];
    const int tid = threadIdx.x;
    const int be = blockIdx.x * 32;
    if (tid < 96) {
        const int e = tid & 31;
        const int d = tid >> 5;
        const int ge = be + e;
        float x = (ge < E) ? fd[ge * 3 + d] : 0.0f;
        float th = 6.28318530717958647692f * x;
        float s1, c1;
        sincosf(th, &s1, &c1);
        int f = e;
        float sf, cf;
        sincosf(th * (float)f, &sf, &cf);
        float* rowS = fs + e * DIS + d * 64;
        float* rowC = rowS + 192;
        for (int i = 0; i < 64; ++i) {
            rowS[f] = sf;
            rowC[f] = cf;
            f++;
            float ns = sf * c1 + cf * s1;
            float nc = cf * c1 - sf * s1;
            bool wrap = (f == 64);
            sf = wrap ? 0.0f : ns;
            cf = wrap ? 1.0f : nc;
            f  = wrap ? 0 : f;
        }
    }
    __syncthreads();
    for (int i = tid; i < 32 * 48; i += 256) {
        int e = i / 48, grp = i % 48;
        if (be + e >= E) continue;
        const float* s = fs + e * DIS + grp * 8;
        us hs[8];
#pragma unroll
        for (int c = 0; c < 8; c++) hs[c] = cvt1(s[c]);
        uint4 v = make_uint4((u32)hs[0] | ((u32)hs[1] << 16), (u32)hs[2] | ((u32)hs[3] << 16),
                             (u32)hs[4] | ((u32)hs[5] << 16), (u32)hs[6] | ((u32)hs[7] << 16));
        ((uint4*)g_femb)[(size_t)(be + e) * 48 + grp] = v;
    }
}

// ============================ HMMA GEMM (fp16, 2-MMA weight split) ============
// Block tile 128(M) x 128(N), 8 warps (4M x 2N), warp tile 32x64.
// A: single fp16 plane (activations). B: fp16 hi/lo planes (weights).
// acc += A*Bh + A*Bl  (= A*B to ~22 bits of weight precision), fp32 accum.
// cp.async double-buffered KC=32 chunks; fragments via ldmatrix.x4.
// Plane layout: 128 rows x 20 words (80B stride, conflict-free ldmatrix).
// MODE 0: Cf[row*ldx+col] = acc
// MODE 1: Ch = fp16(silu(acc + P[src] + Q[dst] + R[e2g]))
// MODE 2: atomicAdd(Cf[src[row]], silu(acc + bias))
// MODE 3: Ch = fp16(silu(rowScale[row]*acc + addRow + bias))
// MODE 4: Cf = addRow + silu(acc + bias)
#define PLANE 10240       // 128 * 20 words * 4B
#define BUFB  30720       // 3 planes (A, Bh, Bl)
#define SMEM_TOTAL 61440  // 2 buffers

template <int MODE>
__global__ __launch_bounds__(256, 1) void tgemm(
    const us* __restrict__ A,
    const us* __restrict__ Bh, const us* __restrict__ Bl,
    int M, int K, int ldx,
    const int* __restrict__ src, const int* __restrict__ dst,
    const int* __restrict__ e2g,
    const float* __restrict__ Pm, const float* __restrict__ Qm,
    const float* __restrict__ Rm,
    const float* __restrict__ bias, const float* __restrict__ rowScale,
    const float* __restrict__ addRow,
    float* __restrict__ Cf, us* __restrict__ Ch) {
    extern __shared__ char smem[];
    const u32 sb = smem_u32(smem);
    const int tid  = threadIdx.x;
    const int lane = tid & 31;
    const int wid  = tid >> 5;
    const int g = lane >> 2, q = lane & 3;
    const int row0  = blockIdx.y * 128;
    const int nbase = blockIdx.x * 128;
    const int mrow0  = (wid & 3) * 32;
    const int nwarp0 = (wid >> 2) * 64;

    const int rowin = lane & 7;
    const int msel  = lane >> 3;
    u32 offA[2];  // [mt]
#pragma unroll
    for (int mt = 0; mt < 2; mt++)
        offA[mt] = (u32)((mrow0 + mt * 16 + rowin + (msel & 1) * 8) * 80 +
                         (msel >> 1) * 16);
    u32 offB[2];  // [plane hi/lo]
#pragma unroll
    for (int pl = 0; pl < 2; pl++)
        offB[pl] = (u32)((1 + pl) * PLANE +
                         (nwarp0 + (msel >> 1) * 8 + rowin) * 80 +
                         (msel & 1) * 16);

    float acc[2][8][4];
#pragma unroll
    for (int a = 0; a < 2; a++)
#pragma unroll
        for (int b = 0; b < 8; b++)
#pragma unroll
            for (int c = 0; c < 4; c++) acc[a][b][c] = 0.0f;

    const int nch = K >> 5;

    auto issue = [&](int ch, int buf) {
        const u32 b0 = sb + buf * BUFB;
#pragma unroll
        for (int j = 0; j < 2; j++) {
            int seg = tid + j * 256;
            int r = seg >> 2, ksg = seg & 3;
            u32 dstp = b0 + (u32)(r * 80 + ksg * 16);
            int ra = row0 + r;
            int sz = (ra < M) ? 16 : 0;
            if (ra >= M) ra = M - 1;
            cpa(dstp, A + (size_t)ra * K + ch * 32 + ksg * 8, sz);
            size_t offb = (size_t)(nbase + r) * K + ch * 32 + ksg * 8;
            cpa(dstp + PLANE,     Bh + offb, 16);
            cpa(dstp + 2 * PLANE, Bl + offb, 16);
        }
        cpcommit();
    };

    issue(0, 0);
    for (int ch = 0; ch < nch; ++ch) {
        bool hasnext = (ch + 1 < nch);
        if (hasnext) issue(ch + 1, (ch + 1) & 1);
        if (hasnext) cpwait<1>(); else cpwait<0>();
        __syncthreads();
        const u32 ab = sb + (ch & 1) * BUFB;
#pragma unroll
        for (int ks = 0; ks < 2; ks++) {
            u32 afr[2][4];
#pragma unroll
            for (int mt = 0; mt < 2; mt++)
                ldmx4(afr[mt], ab + offA[mt] + ks * 32);
#pragma unroll
            for (int nt2 = 0; nt2 < 4; nt2++) {
                u32 bh[4], bl[4];
                ldmx4(bh, ab + offB[0] + nt2 * 1280 + ks * 32);
                ldmx4(bl, ab + offB[1] + nt2 * 1280 + ks * 32);
#pragma unroll
                for (int hv = 0; hv < 2; hv++) {
                    const int nt = nt2 * 2 + hv;
#pragma unroll
                    for (int mt = 0; mt < 2; mt++) {
                        mma16816(acc[mt][nt], afr[mt], bh + 2 * hv);
                        mma16816(acc[mt][nt], afr[mt], bl + 2 * hv);
                    }
                }
            }
        }
        __syncthreads();
    }

    // ---- epilogue ----
#pragma unroll
    for (int mt = 0; mt < 2; mt++) {
#pragma unroll
        for (int h2 = 0; h2 < 2; h2++) {
            int row = row0 + mrow0 + mt * 16 + g + h2 * 8;
            if (row >= M) continue;
            int s = 0, dn = 0, gg = 0;
            float rsc = 0.0f;
            if (MODE == 1) { s = src[row]; dn = dst[row]; gg = e2g[row]; }
            if (MODE == 2) { s = src[row]; }
            if (MODE == 3) { rsc = rowScale[row]; }
#pragma unroll
            for (int nt = 0; nt < 8; nt++) {
                int col = nbase + nwarp0 + nt * 8 + 2 * q;
                float v0 = acc[mt][nt][h2 * 2 + 0];
                float v1 = acc[mt][nt][h2 * 2 + 1];
                if (MODE == 0) {
                    *(float2*)(Cf + (size_t)row * ldx + col) = make_float2(v0, v1);
                } else if (MODE == 1) {
                    float2 p2 = *(const float2*)(Pm + (size_t)s  * ldx + col);
                    float2 q2 = *(const float2*)(Qm + (size_t)dn * ldx + col);
                    float2 r2 = *(const float2*)(Rm + (size_t)gg * 256 + col);
                    us h0 = cvt1(dsilu(v0 + p2.x + q2.x + r2.x));
                    us h1 = cvt1(dsilu(v1 + p2.y + q2.y + r2.y));
                    *(u32*)(Ch + (size_t)row * 256 + col) = (u32)h0 | ((u32)h1 << 16);
                } else if (MODE == 2) {
                    float2 b2 = *(const float2*)(bias + col);
                    atomicAdd(Cf + (size_t)s * 256 + col + 0, dsilu(v0 + b2.x));
                    atomicAdd(Cf + (size_t)s * 256 + col + 1, dsilu(v1 + b2.y));
                } else if (MODE == 3) {
                    float2 b2 = *(const float2*)(bias + col);
                    float2 a2 = *(const float2*)(addRow + (size_t)row * ldx + col);
                    us h0 = cvt1(dsilu(rsc * v0 + a2.x + b2.x));
                    us h1 = cvt1(dsilu(rsc * v1 + a2.y + b2.y));
                    *(u32*)(Ch + (size_t)row * 256 + col) = (u32)h0 | ((u32)h1 << 16);
                } else {  // MODE 4
                    float2 b2 = *(const float2*)(bias + col);
                    float2 a2 = *(const float2*)(addRow + (size_t)row * 256 + col);
                    *(float2*)(Cf + (size_t)row * 256 + col) =
                        make_float2(a2.x + dsilu(v0 + b2.x), a2.y + dsilu(v1 + b2.y));
                }
            }
        }
    }
}

// ============================ host side ============================
static float *p_PQS, *p_R, *p_sums, *p_rcnt;
static int *p_src, *p_dst, *p_e2g;
static us *p_hs, *p_femb, *p_e1, *p_sum16, *p_t1;
static us *p_wPQSh, *p_wPQSl, *p_wFh, *p_wFl;
static us *p_w2h, *p_w2l, *p_wNh, *p_wNl, *p_wOh, *p_wOl;
static bool g_init = false;

static void init_ptrs() {
    if (g_init) return;
    g_init = true;
    cudaGetSymbolAddress((void**)&p_PQS, g_PQS);
    cudaGetSymbolAddress((void**)&p_R, g_R);
    cudaGetSymbolAddress((void**)&p_sums, g_sums);
    cudaGetSymbolAddress((void**)&p_rcnt, g_rcnt);
    cudaGetSymbolAddress((void**)&p_src, g_src);
    cudaGetSymbolAddress((void**)&p_dst, g_dst);
    cudaGetSymbolAddress((void**)&p_e2g, g_e2g);
    cudaGetSymbolAddress((void**)&p_hs, g_hs);
    cudaGetSymbolAddress((void**)&p_femb, g_femb);
    cudaGetSymbolAddress((void**)&p_e1, g_e1);
    cudaGetSymbolAddress((void**)&p_sum16, g_sum16);
    cudaGetSymbolAddress((void**)&p_t1, g_t1);
    cudaGetSymbolAddress((void**)&p_wPQSh, g_wPQSh);
    cudaGetSymbolAddress((void**)&p_wPQSl, g_wPQSl);
    cudaGetSymbolAddress((void**)&p_wFh, g_wFh);
    cudaGetSymbolAddress((void**)&p_wFl, g_wFl);
    cudaGetSymbolAddress((void**)&p_w2h, g_w2h);
    cudaGetSymbolAddress((void**)&p_w2l, g_w2l);
    cudaGetSymbolAddress((void**)&p_wNh, g_wNh);
    cudaGetSymbolAddress((void**)&p_wNl, g_wNl);
    cudaGetSymbolAddress((void**)&p_wOh, g_wOh);
    cudaGetSymbolAddress((void**)&p_wOl, g_wOl);
    cudaFuncSetAttribute(tgemm<0>, cudaFuncAttributeMaxDynamicSharedMemorySize, SMEM_TOTAL);
    cudaFuncSetAttribute(tgemm<1>, cudaFuncAttributeMaxDynamicSharedMemorySize, SMEM_TOTAL);
    cudaFuncSetAttribute(tgemm<2>, cudaFuncAttributeMaxDynamicSharedMemorySize, SMEM_TOTAL);
    cudaFuncSetAttribute(tgemm<3>, cudaFuncAttributeMaxDynamicSharedMemorySize, SMEM_TOTAL);
    cudaFuncSetAttribute(tgemm<4>, cudaFuncAttributeMaxDynamicSharedMemorySize, SMEM_TOTAL);
}
namespace {
struct Boot {
    Boot() { init_ptrs(); }
};
static Boot boot_;
}  // namespace

extern "C" void kernel_launch(void* const* d_in, const int* in_sizes, int n_in,
                              void* d_out, int out_size) {
    init_ptrs();
    const float* nf  = (const float*)d_in[0];
    const float* lat = (const float*)d_in[1];
    const void*  eix = d_in[2];
    const void*  e2g = d_in[3];
    const float* fd  = (const float*)d_in[4];
    const float* gam = (const float*)d_in[6];
    const float* bet = (const float*)d_in[7];
    const float* We1 = (const float*)d_in[8];
    const float* be1 = (const float*)d_in[9];
    const float* We2 = (const float*)d_in[10];
    const float* be2 = (const float*)d_in[11];
    const float* Wn1 = (const float*)d_in[12];
    const float* bn1 = (const float*)d_in[13];
    const float* Wn2 = (const float*)d_in[14];
    const float* bn2 = (const float*)d_in[15];
    float* out = (float*)d_out;

    const int Nn = in_sizes[0] / H;
    const int Gn = in_sizes[1] / 9;
    const int E  = in_sizes[4] / 3;
    const dim3 gN(2, (Nn + 127) / 128);
    const dim3 gN3(6, (Nn + 127) / 128);  // merged P|Q|S, N=768
    const dim3 gE(2, (E + 127) / 128);

    detect_k<<<1, 256>>>(eix, E);
    zero_k<<<(Nn * H + 255) / 256, 256>>>(Nn);
    convert_k<<<(E + 255) / 256, 256>>>(eix, e2g, E);
    ln_k<<<Nn, 256>>>(nf, gam, bet);
    lat_k<<<Gn, 256>>>(lat, We1, be1);
    rcnt_k<<<(Nn + 255) / 256, 256>>>(Nn);

    const int twg = (256 * 256 + 255) / 256;
    tw_k<<<twg, 256>>>(We1, 256, p_wPQSh, p_wPQSl);                                // P
    tw_k<<<twg, 256>>>(We1 + 256 * H, 256, p_wPQSh + 256 * H, p_wPQSl + 256 * H);  // Q
    tw_k<<<twg, 256>>>(Wn1, 256, p_wPQSh + 512 * H, p_wPQSl + 512 * H);            // S
    tw_k<<<(256 * 384 + 255) / 256, 256>>>(We1 + 521 * H, 384, p_wFh, p_wFl);
    tw_k<<<twg, 256>>>(We2, 256, p_w2h, p_w2l);
    tw_k<<<twg, 256>>>(Wn1 + 256 * H, 256, p_wNh, p_wNl);
    tw_k<<<twg, 256>>>(Wn2, 256, p_wOh, p_wOl);

    femb_k<<<(E + 31) / 32, 256>>>(fd, E);

    // merged node precompute: PQS = h @ [We1a | We1b | Wn1a]  (N=768)
    tgemm<0><<<gN3, 256, SMEM_TOTAL>>>(p_hs, p_wPQSh, p_wPQSl, Nn, 256, 768,
                                       0, 0, 0, 0, 0, 0, 0, 0, 0, p_PQS, 0);

    // edge layer 1: e1 = silu(femb@Wf + P[src] + Q[dst] + R[e2g]) -> fp16
    tgemm<1><<<gE, 256, SMEM_TOTAL>>>(p_femb, p_wFh, p_wFl, E, 384, 768,
                                      p_src, p_dst, p_e2g, p_PQS, p_PQS + 256, p_R,
                                      0, 0, 0, 0, p_e1);

    // edge layer 2 + scatter: sums[src] += silu(e1@We2 + be2)
    tgemm<2><<<gE, 256, SMEM_TOTAL>>>(p_e1, p_w2h, p_w2l, E, 256, 256,
                                      p_src, 0, 0, 0, 0, 0,
                                      be2, 0, 0, p_sums, 0);

    cvt_k<<<(Nn * H + 255) / 256, 256>>>(p_sums, p_sum16, Nn * H);

    // node layer 1: t1 = silu(rcnt*(sums@Wn1b) + S + bn1) -> fp16
    tgemm<3><<<gN, 256, SMEM_TOTAL>>>(p_sum16, p_wNh, p_wNl, Nn, 256, 768,
                                      0, 0, 0, 0, 0, 0,
                                      bn1, p_rcnt, p_PQS + 512, 0, p_t1);

    // node layer 2 + residual: out = nf + silu(t1@Wn2 + bn2)
    tgemm<4><<<gN, 256, SMEM_TOTAL>>>(p_t1, p_wOh, p_wOl, Nn, 256, 256,
                                      0, 0, 0, 0, 0, 0,
                                      bn2, 0, nf, out, 0);
}

// round 9
// speedup vs baseline: 4.7737x; 1.2677x over previous
#include <cuda_runtime.h>
#include <cuda_fp16.h>
#include <cstdint>

#define H 256
#define NMAX 20000
#define EMAX 320000
#define GMAX 1000
#define DIS 384

typedef unsigned int u32;
typedef unsigned short us;

// ============================ helpers ============================
__device__ __forceinline__ u32 smem_u32(const void* p) {
    u32 a;
    asm("{ .reg .u64 t; cvta.to.shared.u64 t, %1; cvt.u32.u64 %0, t; }" : "=r"(a) : "l"(p));
    return a;
}
__device__ __forceinline__ void cpa(u32 dst, const void* src, int sz) {
    asm volatile("cp.async.cg.shared.global [%0], [%1], 16, %2;"
                 :: "r"(dst), "l"(src), "r"(sz) : "memory");
}
__device__ __forceinline__ void cpcommit() {
    asm volatile("cp.async.commit_group;" ::: "memory");
}
template <int N>
__device__ __forceinline__ void cpwait() {
    asm volatile("cp.async.wait_group %0;" :: "n"(N) : "memory");
}
__device__ __forceinline__ void ldmx4(u32* r, u32 addr) {
    asm volatile("ldmatrix.sync.aligned.m8n8.x4.shared.b16 {%0,%1,%2,%3}, [%4];"
                 : "=r"(r[0]), "=r"(r[1]), "=r"(r[2]), "=r"(r[3]) : "r"(addr));
}
// m16n8k16 fp16 mma, fp32 accum (arch-neutral HMMA path)
__device__ __forceinline__ void mma16816(float* c, const u32* a, const u32* b) {
    asm volatile(
        "mma.sync.aligned.m16n8k16.row.col.f32.f16.f16.f32 "
        "{%0,%1,%2,%3},{%4,%5,%6,%7},{%8,%9},{%0,%1,%2,%3};"
        : "+f"(c[0]), "+f"(c[1]), "+f"(c[2]), "+f"(c[3])
        : "r"(a[0]), "r"(a[1]), "r"(a[2]), "r"(a[3]), "r"(b[0]), "r"(b[1]));
}
__device__ __forceinline__ float dsilu(float x) {
    return __fdividef(x, 1.0f + __expf(-x));
}
__device__ __forceinline__ us cvt1(float v) {
    __half h = __float2half(v);
    return *reinterpret_cast<us*>(&h);
}

// ============================ device scratch ============================
__device__ int g_is64;
__device__ int g_src[EMAX];
__device__ int g_dst[EMAX];
__device__ int g_e2g[EMAX];
__device__ float g_PQS[(size_t)NMAX * 768];  // P | Q | S per row
__device__ float g_R[GMAX * H];
__device__ float g_sums[NMAX * H];
__device__ float g_cnt[NMAX];
__device__ float g_rcnt[NMAX];
// fp16 activations
__device__ us g_hs[NMAX * H];
__device__ us g_femb[(size_t)EMAX * DIS];
__device__ us g_e1[(size_t)EMAX * H];
__device__ us g_sum16[NMAX * H];
__device__ us g_t1[NMAX * H];
// fp16 transposed weights Bt[n][k]
__device__ us g_wPQS[768 * H];
__device__ us g_wF[H * DIS];
__device__ us g_w2[H * H];
__device__ us g_wN[H * H];
__device__ us g_wO[H * H];

// ============================ small kernels ============================
__global__ void detect_k(const void* eidx, int E) {
    __shared__ int any;
    if (threadIdx.x == 0) any = 0;
    __syncthreads();
    const int* w = (const int*)eidx;
    int lim = 2048 < (E - 1) ? 2048 : (E - 1);
    for (int i = threadIdx.x; i < lim; i += blockDim.x)
        if (w[2 * i + 1] != 0) any = 1;
    __syncthreads();
    if (threadIdx.x == 0) g_is64 = (any == 0) ? 1 : 0;
}

__global__ void convert_k(const void* eidx, const void* e2g, int E) {
    int i = blockIdx.x * blockDim.x + threadIdx.x;
    if (i >= E) return;
    int s;
    if (g_is64) {
        const long long* p = (const long long*)eidx;
        const long long* q = (const long long*)e2g;
        s = (int)p[i];
        g_dst[i] = (int)p[(size_t)E + i];
        g_e2g[i] = (int)q[i];
    } else {
        const int* p = (const int*)eidx;
        const int* q = (const int*)e2g;
        s = p[i];
        g_dst[i] = p[E + i];
        g_e2g[i] = q[i];
    }
    g_src[i] = s;
    atomicAdd(&g_cnt[s], 1.0f);
}

__global__ void zero_k(int Nn) {
    int i = blockIdx.x * blockDim.x + threadIdx.x;
    if (i < Nn * H) g_sums[i] = 0.0f;
    if (i < Nn) g_cnt[i] = 0.0f;
}

__global__ void rcnt_k(int Nn) {
    int i = blockIdx.x * blockDim.x + threadIdx.x;
    if (i < Nn) g_rcnt[i] = 1.0f / fmaxf(g_cnt[i], 1.0f);
}

__global__ __launch_bounds__(256) void ln_k(const float* __restrict__ x,
                                            const float* __restrict__ gm,
                                            const float* __restrict__ bt) {
    int row = blockIdx.x;
    int c = threadIdx.x;
    float v = x[(size_t)row * H + c];
    float s = v, ss = v * v;
#pragma unroll
    for (int o = 16; o; o >>= 1) {
        s  += __shfl_xor_sync(0xffffffffu, s, o);
        ss += __shfl_xor_sync(0xffffffffu, ss, o);
    }
    __shared__ float as[8], bs[8];
    if ((c & 31) == 0) { as[c >> 5] = s; bs[c >> 5] = ss; }
    __syncthreads();
    s = 0.f; ss = 0.f;
#pragma unroll
    for (int i = 0; i < 8; i++) { s += as[i]; ss += bs[i]; }
    float mu  = s * (1.0f / H);
    float var = ss * (1.0f / H) - mu * mu;
    float inv = rsqrtf(var + 1e-5f);
    g_hs[(size_t)row * H + c] = cvt1((v - mu) * inv * gm[c] + bt[c]);
}

__global__ __launch_bounds__(256) void lat_k(const float* __restrict__ L,
                                             const float* __restrict__ We1,
                                             const float* __restrict__ be1) {
    int g = blockIdx.x;
    __shared__ float ll[9];
    if (threadIdx.x < 9) {
        int i = threadIdx.x / 3, k = threadIdx.x % 3;
        const float* Lg = L + g * 9;
        ll[threadIdx.x] = Lg[i * 3 + 0] * Lg[k * 3 + 0] +
                          Lg[i * 3 + 1] * Lg[k * 3 + 1] +
                          Lg[i * 3 + 2] * Lg[k * 3 + 2];
    }
    __syncthreads();
    int c = threadIdx.x;
    float a = be1[c];
#pragma unroll
    for (int p = 0; p < 9; p++) a += ll[p] * We1[(512 + p) * H + c];
    g_R[g * H + c] = a;
}

// weight transpose -> fp16: Bt[n][k] = fp16(W[k][n])
__global__ void tw_k(const float* __restrict__ W, int K, us* __restrict__ o) {
    int idx = blockIdx.x * blockDim.x + threadIdx.x;
    if (idx >= 256 * K) return;
    int n = idx / K, k = idx % K;
    o[idx] = cvt1(W[(size_t)k * 256 + n]);
}

__global__ void cvt_k(const float* __restrict__ in, us* __restrict__ o, int n) {
    int i = blockIdx.x * blockDim.x + threadIdx.x;
    if (i < n) o[i] = cvt1(in[i]);
}

// sinusoid embedding via angle-addition recurrence -> fp16
__global__ __launch_bounds__(256) void femb_k(const float* __restrict__ fd, int E) {
    __shared__ float fs[32 * DIS];
    const int tid = threadIdx.x;
    const int be = blockIdx.x * 32;
    if (tid < 96) {
        const int e = tid & 31;
        const int d = tid >> 5;
        const int ge = be + e;
        float x = (ge < E) ? fd[ge * 3 + d] : 0.0f;
        float th = 6.28318530717958647692f * x;
        float s1, c1;
        sincosf(th, &s1, &c1);
        int f = e;
        float sf, cf;
        sincosf(th * (float)f, &sf, &cf);
        float* rowS = fs + e * DIS + d * 64;
        float* rowC = rowS + 192;
        for (int i = 0; i < 64; ++i) {
            rowS[f] = sf;
            rowC[f] = cf;
            f++;
            float ns = sf * c1 + cf * s1;
            float nc = cf * c1 - sf * s1;
            bool wrap = (f == 64);
            sf = wrap ? 0.0f : ns;
            cf = wrap ? 1.0f : nc;
            f  = wrap ? 0 : f;
        }
    }
    __syncthreads();
    for (int i = tid; i < 32 * 48; i += 256) {
        int e = i / 48, grp = i % 48;
        if (be + e >= E) continue;
        const float* s = fs + e * DIS + grp * 8;
        us hs[8];
#pragma unroll
        for (int c = 0; c < 8; c++) hs[c] = cvt1(s[c]);
        uint4 v = make_uint4((u32)hs[0] | ((u32)hs[1] << 16), (u32)hs[2] | ((u32)hs[3] << 16),
                             (u32)hs[4] | ((u32)hs[5] << 16), (u32)hs[6] | ((u32)hs[7] << 16));
        ((uint4*)g_femb)[(size_t)(be + e) * 48 + grp] = v;
    }
}

// ============================ HMMA GEMM (fp16 single-plane) =================
// Block tile 128(M) x 128(N), 8 warps (4M x 2N), warp tile 32x64.
// A, B both single fp16 planes; 1 MMA per (mt,nt) k-step; fp32 accum.
// cp.async double-buffered KC=32 chunks; fragments via ldmatrix.x4.
// Plane layout: 128 rows x 20 words (80B stride, conflict-free ldmatrix).
// MODE 0: Cf[row*ldx+col] = acc
// MODE 1: Ch = fp16(silu(acc + P[src] + Q[dst] + R[e2g]))
// MODE 2: atomicAdd(Cf[src[row]], silu(acc + bias))
// MODE 3: Ch = fp16(silu(rowScale[row]*acc + addRow + bias))
// MODE 4: Cf = addRow + silu(acc + bias)
#define PLANE 10240       // 128 * 20 words * 4B
#define BUFB  20480       // 2 planes (A, B)
#define SMEM_TOTAL 40960  // 2 buffers

template <int MODE>
__global__ __launch_bounds__(256, 2) void tgemm(
    const us* __restrict__ A, const us* __restrict__ B,
    int M, int K, int ldx,
    const int* __restrict__ src, const int* __restrict__ dst,
    const int* __restrict__ e2g,
    const float* __restrict__ Pm, const float* __restrict__ Qm,
    const float* __restrict__ Rm,
    const float* __restrict__ bias, const float* __restrict__ rowScale,
    const float* __restrict__ addRow,
    float* __restrict__ Cf, us* __restrict__ Ch) {
    extern __shared__ char smem[];
    const u32 sb = smem_u32(smem);
    const int tid  = threadIdx.x;
    const int lane = tid & 31;
    const int wid  = tid >> 5;
    const int g = lane >> 2, q = lane & 3;
    const int row0  = blockIdx.y * 128;
    const int nbase = blockIdx.x * 128;
    const int mrow0  = (wid & 3) * 32;
    const int nwarp0 = (wid >> 2) * 64;

    const int rowin = lane & 7;
    const int msel  = lane >> 3;
    u32 offA[2];  // [mt]
#pragma unroll
    for (int mt = 0; mt < 2; mt++)
        offA[mt] = (u32)((mrow0 + mt * 16 + rowin + (msel & 1) * 8) * 80 +
                         (msel >> 1) * 16);
    const u32 offB = (u32)(PLANE + (nwarp0 + (msel >> 1) * 8 + rowin) * 80 +
                           (msel & 1) * 16);

    float acc[2][8][4];
#pragma unroll
    for (int a = 0; a < 2; a++)
#pragma unroll
        for (int b = 0; b < 8; b++)
#pragma unroll
            for (int c = 0; c < 4; c++) acc[a][b][c] = 0.0f;

    const int nch = K >> 5;

    auto issue = [&](int ch, int buf) {
        const u32 b0 = sb + buf * BUFB;
#pragma unroll
        for (int j = 0; j < 2; j++) {
            int seg = tid + j * 256;
            int r = seg >> 2, ksg = seg & 3;
            u32 dstp = b0 + (u32)(r * 80 + ksg * 16);
            int ra = row0 + r;
            int sz = (ra < M) ? 16 : 0;
            if (ra >= M) ra = M - 1;
            cpa(dstp, A + (size_t)ra * K + ch * 32 + ksg * 8, sz);
            cpa(dstp + PLANE, B + (size_t)(nbase + r) * K + ch * 32 + ksg * 8, 16);
        }
        cpcommit();
    };

    issue(0, 0);
    for (int ch = 0; ch < nch; ++ch) {
        bool hasnext = (ch + 1 < nch);
        if (hasnext) issue(ch + 1, (ch + 1) & 1);
        if (hasnext) cpwait<1>(); else cpwait<0>();
        __syncthreads();
        const u32 ab = sb + (ch & 1) * BUFB;
#pragma unroll
        for (int ks = 0; ks < 2; ks++) {
            u32 afr[2][4];
#pragma unroll
            for (int mt = 0; mt < 2; mt++)
                ldmx4(afr[mt], ab + offA[mt] + ks * 32);
#pragma unroll
            for (int nt2 = 0; nt2 < 4; nt2++) {
                u32 bf[4];
                ldmx4(bf, ab + offB + nt2 * 1280 + ks * 32);
#pragma unroll
                for (int hv = 0; hv < 2; hv++) {
                    const int nt = nt2 * 2 + hv;
#pragma unroll
                    for (int mt = 0; mt < 2; mt++)
                        mma16816(acc[mt][nt], afr[mt], bf + 2 * hv);
                }
            }
        }
        __syncthreads();
    }

    // ---- epilogue ----
#pragma unroll
    for (int mt = 0; mt < 2; mt++) {
#pragma unroll
        for (int h2 = 0; h2 < 2; h2++) {
            int row = row0 + mrow0 + mt * 16 + g + h2 * 8;
            if (row >= M) continue;
            int s = 0, dn = 0, gg = 0;
            float rsc = 0.0f;
            if (MODE == 1) { s = src[row]; dn = dst[row]; gg = e2g[row]; }
            if (MODE == 2) { s = src[row]; }
            if (MODE == 3) { rsc = rowScale[row]; }
#pragma unroll
            for (int nt = 0; nt < 8; nt++) {
                int col = nbase + nwarp0 + nt * 8 + 2 * q;
                float v0 = acc[mt][nt][h2 * 2 + 0];
                float v1 = acc[mt][nt][h2 * 2 + 1];
                if (MODE == 0) {
                    *(float2*)(Cf + (size_t)row * ldx + col) = make_float2(v0, v1);
                } else if (MODE == 1) {
                    float2 p2 = *(const float2*)(Pm + (size_t)s  * ldx + col);
                    float2 q2 = *(const float2*)(Qm + (size_t)dn * ldx + col);
                    float2 r2 = *(const float2*)(Rm + (size_t)gg * 256 + col);
                    us h0 = cvt1(dsilu(v0 + p2.x + q2.x + r2.x));
                    us h1 = cvt1(dsilu(v1 + p2.y + q2.y + r2.y));
                    *(u32*)(Ch + (size_t)row * 256 + col) = (u32)h0 | ((u32)h1 << 16);
                } else if (MODE == 2) {
                    float2 b2 = *(const float2*)(bias + col);
                    atomicAdd(Cf + (size_t)s * 256 + col + 0, dsilu(v0 + b2.x));
                    atomicAdd(Cf + (size_t)s * 256 + col + 1, dsilu(v1 + b2.y));
                } else if (MODE == 3) {
                    float2 b2 = *(const float2*)(bias + col);
                    float2 a2 = *(const float2*)(addRow + (size_t)row * ldx + col);
                    us h0 = cvt1(dsilu(rsc * v0 + a2.x + b2.x));
                    us h1 = cvt1(dsilu(rsc * v1 + a2.y + b2.y));
                    *(u32*)(Ch + (size_t)row * 256 + col) = (u32)h0 | ((u32)h1 << 16);
                } else {  // MODE 4
                    float2 b2 = *(const float2*)(bias + col);
                    float2 a2 = *(const float2*)(addRow + (size_t)row * 256 + col);
                    *(float2*)(Cf + (size_t)row * 256 + col) =
                        make_float2(a2.x + dsilu(v0 + b2.x), a2.y + dsilu(v1 + b2.y));
                }
            }
        }
    }
}

// ============================ host side ============================
static float *p_PQS, *p_R, *p_sums, *p_rcnt;
static int *p_src, *p_dst, *p_e2g;
static us *p_hs, *p_femb, *p_e1, *p_sum16, *p_t1;
static us *p_wPQS, *p_wF, *p_w2, *p_wN, *p_wO;
static bool g_init = false;

static void init_ptrs() {
    if (g_init) return;
    g_init = true;
    cudaGetSymbolAddress((void**)&p_PQS, g_PQS);
    cudaGetSymbolAddress((void**)&p_R, g_R);
    cudaGetSymbolAddress((void**)&p_sums, g_sums);
    cudaGetSymbolAddress((void**)&p_rcnt, g_rcnt);
    cudaGetSymbolAddress((void**)&p_src, g_src);
    cudaGetSymbolAddress((void**)&p_dst, g_dst);
    cudaGetSymbolAddress((void**)&p_e2g, g_e2g);
    cudaGetSymbolAddress((void**)&p_hs, g_hs);
    cudaGetSymbolAddress((void**)&p_femb, g_femb);
    cudaGetSymbolAddress((void**)&p_e1, g_e1);
    cudaGetSymbolAddress((void**)&p_sum16, g_sum16);
    cudaGetSymbolAddress((void**)&p_t1, g_t1);
    cudaGetSymbolAddress((void**)&p_wPQS, g_wPQS);
    cudaGetSymbolAddress((void**)&p_wF, g_wF);
    cudaGetSymbolAddress((void**)&p_w2, g_w2);
    cudaGetSymbolAddress((void**)&p_wN, g_wN);
    cudaGetSymbolAddress((void**)&p_wO, g_wO);
    cudaFuncSetAttribute(tgemm<0>, cudaFuncAttributeMaxDynamicSharedMemorySize, SMEM_TOTAL);
    cudaFuncSetAttribute(tgemm<1>, cudaFuncAttributeMaxDynamicSharedMemorySize, SMEM_TOTAL);
    cudaFuncSetAttribute(tgemm<2>, cudaFuncAttributeMaxDynamicSharedMemorySize, SMEM_TOTAL);
    cudaFuncSetAttribute(tgemm<3>, cudaFuncAttributeMaxDynamicSharedMemorySize, SMEM_TOTAL);
    cudaFuncSetAttribute(tgemm<4>, cudaFuncAttributeMaxDynamicSharedMemorySize, SMEM_TOTAL);
}
namespace {
struct Boot {
    Boot() { init_ptrs(); }
};
static Boot boot_;
}  // namespace

extern "C" void kernel_launch(void* const* d_in, const int* in_sizes, int n_in,
                              void* d_out, int out_size) {
    init_ptrs();
    const float* nf  = (const float*)d_in[0];
    const float* lat = (const float*)d_in[1];
    const void*  eix = d_in[2];
    const void*  e2g = d_in[3];
    const float* fd  = (const float*)d_in[4];
    const float* gam = (const float*)d_in[6];
    const float* bet = (const float*)d_in[7];
    const float* We1 = (const float*)d_in[8];
    const float* be1 = (const float*)d_in[9];
    const float* We2 = (const float*)d_in[10];
    const float* be2 = (const float*)d_in[11];
    const float* Wn1 = (const float*)d_in[12];
    const float* bn1 = (const float*)d_in[13];
    const float* Wn2 = (const float*)d_in[14];
    const float* bn2 = (const float*)d_in[15];
    float* out = (float*)d_out;

    const int Nn = in_sizes[0] / H;
    const int Gn = in_sizes[1] / 9;
    const int E  = in_sizes[4] / 3;
    const dim3 gN(2, (Nn + 127) / 128);
    const dim3 gN3(6, (Nn + 127) / 128);  // merged P|Q|S, N=768
    const dim3 gE(2, (E + 127) / 128);

    detect_k<<<1, 256>>>(eix, E);
    zero_k<<<(Nn * H + 255) / 256, 256>>>(Nn);
    convert_k<<<(E + 255) / 256, 256>>>(eix, e2g, E);
    ln_k<<<Nn, 256>>>(nf, gam, bet);
    lat_k<<<Gn, 256>>>(lat, We1, be1);
    rcnt_k<<<(Nn + 255) / 256, 256>>>(Nn);

    const int twg = (256 * 256 + 255) / 256;
    tw_k<<<twg, 256>>>(We1, 256, p_wPQS);                        // P
    tw_k<<<twg, 256>>>(We1 + 256 * H, 256, p_wPQS + 256 * H);    // Q
    tw_k<<<twg, 256>>>(Wn1, 256, p_wPQS + 512 * H);              // S
    tw_k<<<(256 * 384 + 255) / 256, 256>>>(We1 + 521 * H, 384, p_wF);
    tw_k<<<twg, 256>>>(We2, 256, p_w2);
    tw_k<<<twg, 256>>>(Wn1 + 256 * H, 256, p_wN);
    tw_k<<<twg, 256>>>(Wn2, 256, p_wO);

    femb_k<<<(E + 31) / 32, 256>>>(fd, E);

    // merged node precompute: PQS = h @ [We1a | We1b | Wn1a]  (N=768)
    tgemm<0><<<gN3, 256, SMEM_TOTAL>>>(p_hs, p_wPQS, Nn, 256, 768,
                                       0, 0, 0, 0, 0, 0, 0, 0, 0, p_PQS, 0);

    // edge layer 1: e1 = silu(femb@Wf + P[src] + Q[dst] + R[e2g]) -> fp16
    tgemm<1><<<gE, 256, SMEM_TOTAL>>>(p_femb, p_wF, E, 384, 768,
                                      p_src, p_dst, p_e2g, p_PQS, p_PQS + 256, p_R,
                                      0, 0, 0, 0, p_e1);

    // edge layer 2 + scatter: sums[src] += silu(e1@We2 + be2)
    tgemm<2><<<gE, 256, SMEM_TOTAL>>>(p_e1, p_w2, E, 256, 256,
                                      p_src, 0, 0, 0, 0, 0,
                                      be2, 0, 0, p_sums, 0);

    cvt_k<<<(Nn * H + 255) / 256, 256>>>(p_sums, p_sum16, Nn * H);

    // node layer 1: t1 = silu(rcnt*(sums@Wn1b) + S + bn1) -> fp16
    tgemm<3><<<gN, 256, SMEM_TOTAL>>>(p_sum16, p_wN, Nn, 256, 768,
                                      0, 0, 0, 0, 0, 0,
                                      bn1, p_rcnt, p_PQS + 512, 0, p_t1);

    // node layer 2 + residual: out = nf + silu(t1@Wn2 + bn2)
    tgemm<4><<<gN, 256, SMEM_TOTAL>>>(p_t1, p_wO, Nn, 256, 256,
                                      0, 0, 0, 0, 0, 0,
                                      bn2, 0, nf, out, 0);
}